// round 11
// baseline (speedup 1.0000x reference)
#include <cuda_runtime.h>
#include <cstdint>
#include <math.h>

#define NN 512

#if defined(__CUDA_ARCH_FEAT_SM103_ALL) || defined(__CUDA_ARCH_FEAT_SM100_ALL)
#define HAS_TCGEN05 1
#else
#define HAS_TCGEN05 0
#endif

// ---------------- device scratch ----------------
__device__ float g_h[NN * 16];
__device__ float g_hi[NN * 64];
__device__ float g_hj[NN * 64];
__device__ float g_ysum_part[4 * NN * 64];

// ---------------- PTX helpers ----------------
__device__ __forceinline__ uint32_t smem_u32(const void* p) {
    uint32_t a;
    asm("{ .reg .u64 t; cvta.to.shared.u64 t, %1; cvt.u32.u64 %0, t; }" : "=r"(a) : "l"(p));
    return a;
}
__device__ __forceinline__ float tf32_rna(float x) {
    float r;
    asm("cvt.rna.tf32.f32 %0, %1;" : "=f"(r) : "f"(x));
    return r;
}
__device__ __forceinline__ uint32_t sw128(uint32_t b) { return b ^ ((b >> 3) & 0x70); }
__device__ __forceinline__ float sigmoidf(float x) { return 1.0f / (1.0f + expf(-x)); }

#if HAS_TCGEN05
// ---- packed f32x2 ----
__device__ __forceinline__ unsigned long long pk2(float lo, float hi) {
    unsigned long long r;
    asm("mov.b64 %0, {%1, %2};" : "=l"(r) : "f"(lo), "f"(hi));
    return r;
}
__device__ __forceinline__ unsigned long long add2(unsigned long long a, unsigned long long b) {
    unsigned long long r;
    asm("add.rn.f32x2 %0, %1, %2;" : "=l"(r) : "l"(a), "l"(b));
    return r;
}
__device__ __forceinline__ unsigned long long fma2v(unsigned long long a, unsigned long long b,
                                                   unsigned long long c) {
    unsigned long long r;
    asm("fma.rn.f32x2 %0, %1, %2, %3;" : "=l"(r) : "l"(a), "l"(b), "l"(c));
    return r;
}
__device__ __forceinline__ float2 upk2(unsigned long long v) {
    float2 f;
    asm("mov.b64 {%0, %1}, %2;" : "=f"(f.x), "=f"(f.y) : "l"(v));
    return f;
}

__device__ __forceinline__ uint32_t elect_one() {
    uint32_t p;
    asm volatile("{ .reg .pred p; elect.sync _|p, 0xFFFFFFFF; selp.b32 %0, 1, 0, p; }" : "=r"(p));
    return p;
}
#define MBARRIER_INIT(addr, cnt) \
    asm volatile("mbarrier.init.shared.b64 [%0], %1;" :: "r"((uint32_t)(addr)), "r"((uint32_t)(cnt)) : "memory")
#define MBARRIER_INVAL(addr) \
    asm volatile("mbarrier.inval.shared.b64 [%0];" :: "r"((uint32_t)(addr)) : "memory")
#define MBARRIER_ARRIVE(addr) \
    asm volatile("mbarrier.arrive.shared.b64 _, [%0];" :: "r"((uint32_t)(addr)) : "memory")
#define MBARRIER_WAIT_PARITY(mbar_smem_addr, phase_parity) do { \
    uint32_t _mbar = (uint32_t)(mbar_smem_addr); \
    uint32_t _parity = (uint32_t)(phase_parity); \
    uint32_t _done; \
    asm volatile( \
        "{\n\t.reg .pred p;\n\t" \
        "mbarrier.try_wait.parity.acquire.cta.shared::cta.b64 p, [%1], %2;\n\t" \
        "selp.b32 %0, 1, 0, p;\n\t}" \
        : "=r"(_done) : "r"(_mbar), "r"(_parity) : "memory"); \
    if (!_done) { \
        asm volatile( \
            "{\n\t.reg .pred P1;\n\t" \
            "WAIT_LOOP_%=:\n\t" \
            "mbarrier.try_wait.parity.acquire.cta.shared::cta.b64 P1, [%0], %1, 0x989680;\n\t" \
            "@P1 bra.uni WAIT_DONE_%=;\n\t" \
            "bra.uni WAIT_LOOP_%=;\n\t" \
            "WAIT_DONE_%=:\n\t}" \
            :: "r"(_mbar), "r"(_parity) : "memory"); \
    } \
} while(0)
#define TCGEN05_ALLOC(saddr, ncols) \
    asm volatile("tcgen05.alloc.cta_group::1.sync.aligned.shared::cta.b32 [%0], %1;" \
                 :: "r"((uint32_t)(saddr)), "r"((uint32_t)(ncols)) : "memory")
#define TCGEN05_DEALLOC(taddr, ncols) \
    asm volatile("tcgen05.dealloc.cta_group::1.sync.aligned.b32 %0, %1;" :: "r"(taddr), "r"((uint32_t)(ncols)))
#define TCGEN05_RELINQ() \
    asm volatile("tcgen05.relinquish_alloc_permit.cta_group::1.sync.aligned;")
#define TCGEN05_COMMIT(mbar) \
    asm volatile("tcgen05.commit.cta_group::1.mbarrier::arrive::one.shared::cluster.b64 [%0];" \
                 :: "r"((uint32_t)(mbar)) : "memory")
#define TCGEN05_FENCE_AFTER()  asm volatile("tcgen05.fence::after_thread_sync;" ::: "memory")
#define TCGEN05_FENCE_BEFORE() asm volatile("tcgen05.fence::before_thread_sync;" ::: "memory")
#define TCGEN05_WAIT_LD()      asm volatile("tcgen05.wait::ld.sync.aligned;" ::: "memory")
#define FENCE_PROXY_ASYNC()    asm volatile("fence.proxy.async.shared::cta;" ::: "memory")

#define TCGEN05_LD_32X32B_X32(r, tmem_addr) \
    asm volatile( \
        "tcgen05.ld.sync.aligned.32x32b.x32.b32 " \
        "{%0, %1, %2, %3, %4, %5, %6, %7, " \
        " %8, %9, %10, %11, %12, %13, %14, %15, " \
        " %16, %17, %18, %19, %20, %21, %22, %23, " \
        " %24, %25, %26, %27, %28, %29, %30, %31}, [%32];" \
        : "=r"((r)[0]),  "=r"((r)[1]),  "=r"((r)[2]),  "=r"((r)[3]), \
          "=r"((r)[4]),  "=r"((r)[5]),  "=r"((r)[6]),  "=r"((r)[7]), \
          "=r"((r)[8]),  "=r"((r)[9]),  "=r"((r)[10]), "=r"((r)[11]), \
          "=r"((r)[12]), "=r"((r)[13]), "=r"((r)[14]), "=r"((r)[15]), \
          "=r"((r)[16]), "=r"((r)[17]), "=r"((r)[18]), "=r"((r)[19]), \
          "=r"((r)[20]), "=r"((r)[21]), "=r"((r)[22]), "=r"((r)[23]), \
          "=r"((r)[24]), "=r"((r)[25]), "=r"((r)[26]), "=r"((r)[27]), \
          "=r"((r)[28]), "=r"((r)[29]), "=r"((r)[30]), "=r"((r)[31]) \
        : "r"(tmem_addr))

// SMEM descriptor: SW128, Blackwell (version=1), SBO=64, LBO=1
static __device__ __forceinline__ uint64_t make_desc(uint32_t addr) {
    const uint64_t base = (uint64_t(2) << 61) | (uint64_t(1) << 46) |
                          (uint64_t(64) << 32) | (uint64_t(1) << 16);
    return base | ((uint64_t)(addr >> 4) & 0x3FFF);
}

// tcgen05.mma kind::tf32, SS, cta_group::1
__device__ __forceinline__ void mma_tf32_ss(uint32_t d, uint64_t ad, uint64_t bd,
                                            uint32_t idesc, bool acc) {
    uint32_t en = acc ? 1u : 0u;
    asm volatile(
        "{\n\t.reg .pred p;\n\t"
        "setp.ne.u32 p, %5, 0;\n\t"
        "tcgen05.mma.cta_group::1.kind::tf32 [%0], %1, %2, %3, {%4, %4, %4, %4}, p;\n\t}"
        :: "r"(d), "l"(ad), "l"(bd), "r"(idesc), "r"(0u), "r"(en) : "memory");
}

// idesc: c=F32(1@[4]), a=TF32(2@[7]), b=TF32(2@[10]), N=64 (8@[17]), M=128 (8@[24])
#define IDESC_TF32 ((1u << 4) | (2u << 7) | (2u << 10) | (8u << 17) | (8u << 24))
#endif  // HAS_TCGEN05

// ---------------- SMEM layout (edge kernel, dynamic) ----------------
// Double-buffered U: bank b at b*32768 (32 KB each)
#define OFF_WHI  65536       // 64x64 f32 swizzled (16384)
#define OFF_WLO  81920
#define OFF_HJ   98304       // 16x64 f32 (4096)
#define OFF_WJ   102400      // 64 f32
#define OFF_B2   102656      // 64 f32
#define OFF_TPTR 102912
#define OFF_MBAR 102928      // 6 mbarriers: ufull[2], mdone[2], edone[2]
#define SMEM_EDGE 102976
// fallback-only offsets (reuse U buffer space)
#define OFF_FHI  32768
#define OFF_FJ   33792

#define NTHR 384

// ============================================================
// Init: h0 = 0; hi/hj terms for h=0
// ============================================================
__global__ void init_kernel(const float* __restrict__ b, const float* __restrict__ W1,
                            const float* __restrict__ b1) {
    int idx = blockIdx.x * 256 + threadIdx.x;
    int node = idx >> 6, c = idx & 63;
    g_hi[idx] = b[node] * W1[c * 35 + 33];
    g_hj[idx] = fmaf(b[node], W1[c * 35 + 34], b1[c]);
    if (c < 16) g_h[node * 16 + c] = 0.0f;
}

// ============================================================
// Edge kernel: warp-specialized tcgen05 tf32 (2-pass W split)
//   warps 0-7:  U producers (1 i-row each)
//   warps 8-11: per-subpartition consumers; warp 8 issues MMAs.
// grid (32 j-tiles, 4 i-chunks), block 384, 1 CTA/SM (balanced)
// ============================================================
__global__ __launch_bounds__(NTHR, 1) void edge_tc_kernel(const float* __restrict__ J,
                                                          const float* __restrict__ W1,
                                                          const float* __restrict__ W2,
                                                          const float* __restrict__ b2) {
    extern __shared__ __align__(1024) char smem[];
    const int t = threadIdx.x;
    const int jt = blockIdx.x, ic = blockIdx.y;
    const int j0 = jt * 16;

    float* sHj = (float*)(smem + OFF_HJ);
    float* swJ = (float*)(smem + OFF_WJ);
    float* sB2 = (float*)(smem + OFF_B2);

#if HAS_TCGEN05
    const uint32_t sbase = smem_u32(smem);
    const int wid = t >> 5, lid = t & 31;

    if (wid == 0) {
        TCGEN05_ALLOC(sbase + OFF_TPTR, 128);
        TCGEN05_RELINQ();
    }
    if (t == 0) {
        MBARRIER_INIT(sbase + OFF_MBAR + 0, 8);   // ufull[0]
        MBARRIER_INIT(sbase + OFF_MBAR + 8, 8);   // ufull[1]
        MBARRIER_INIT(sbase + OFF_MBAR + 16, 1);  // mdone[0]
        MBARRIER_INIT(sbase + OFF_MBAR + 24, 1);  // mdone[1]
        MBARRIER_INIT(sbase + OFF_MBAR + 32, 4);  // edone[0]
        MBARRIER_INIT(sbase + OFF_MBAR + 40, 4);  // edone[1]
    }

    // stage W2 hi/lo (SW128 blocked atoms) — keep rna split here
    for (int idx = t; idx < 4096; idx += NTHR) {
        int c = idx >> 6, k = idx & 63;
        float w = W2[c * 64 + k];
        float whi = tf32_rna(w);
        float wlo = w - whi;
        uint32_t byte = (((c >> 3) + ((k >> 5) << 3)) << 10) + ((c & 7) << 7) + ((k & 31) << 2);
        byte = sw128(byte);
        *(float*)(smem + OFF_WHI + byte) = whi;
        *(float*)(smem + OFF_WLO + byte) = wlo;
    }
    if (t < 64) { swJ[t] = W1[t * 35 + 32]; sB2[t] = b2[t]; }
    for (int idx = t; idx < 1024; idx += NTHR) {
        sHj[idx] = g_hj[(j0 + (idx >> 6)) * 64 + (idx & 63)];
    }
    FENCE_PROXY_ASYNC();
    __syncthreads();

    const uint32_t tmem = *(volatile uint32_t*)(smem + OFF_TPTR);
    const uint32_t mb_ufull = sbase + OFF_MBAR;
    const uint32_t mb_mdone = sbase + OFF_MBAR + 16;
    const uint32_t mb_edone = sbase + OFF_MBAR + 32;

    if (wid < 8) {
        // ================= producer warps (1 i-row each) =================
        const int k0 = (lid & 15) * 4;
        const unsigned long long wq2a = pk2(swJ[k0], swJ[k0 + 1]);
        const unsigned long long wq2b = pk2(swJ[k0 + 2], swJ[k0 + 3]);
        const uint32_t kpart = ((uint32_t)(k0 >> 5) << 14) + ((k0 & 31) << 2);
        const int jhalf = lid >> 4;
        const int ebase = wid * 16;
        const int ibase = ic * 128;

        float4 hv = *(const float4*)&g_hi[(ibase + wid) * 64 + k0];
        float jp = J[(ibase + wid) * NN + j0 + (lid & 15)];

        for (int r = 0; r < 16; r++) {
            const int b = r & 1;
            if (r >= 2) MBARRIER_WAIT_PARITY(mb_mdone + b * 8, ((r - 2) >> 1) & 1);
            char* ubase = smem + b * 32768;
            const unsigned long long hv2a = pk2(hv.x, hv.y);
            const unsigned long long hv2b = pk2(hv.z, hv.w);
#pragma unroll
            for (int m = 0; m < 8; m++) {
                const int jj = 2 * m + jhalf;
                const float Jv = __shfl_sync(0xFFFFFFFFu, jp, jj);
                const ulonglong2 hj2 = *(const ulonglong2*)&sHj[jj * 64 + k0];
                const unsigned long long jv2 = pk2(Jv, Jv);
                unsigned long long t0 = fma2v(jv2, wq2a, add2(hv2a, hj2.x));
                unsigned long long t1 = fma2v(jv2, wq2b, add2(hv2b, hj2.y));
                const float2 a = upk2(t0);
                const float2 c = upk2(t1);
                const int e = ebase + jj;
                float4 u;
                u.x = fmaxf(a.x, 0.0f);
                u.y = fmaxf(a.y, 0.0f);
                u.z = fmaxf(c.x, 0.0f);
                u.w = fmaxf(c.y, 0.0f);
                uint32_t byte = ((uint32_t)(e >> 3) << 10) + ((e & 7) << 7) + kpart;
                byte = sw128(byte);
                *(float4*)(ubase + byte) = u;
            }
            float4 hn = make_float4(0.f, 0.f, 0.f, 0.f);
            float jn = 0.f;
            if (r < 15) {
                const int i0n = ibase + (r + 1) * 8 + wid;
                hn = *(const float4*)&g_hi[i0n * 64 + k0];
                jn = J[i0n * NN + j0 + (lid & 15)];
            }
            FENCE_PROXY_ASYNC();
            __syncwarp();
            if (lid == 0) MBARRIER_ARRIVE(mb_ufull + b * 8);
            hv = hn; jp = jn;
        }
    } else {
        // ================= consumer warps (wid 8-11) =================
        const uint64_t dBhi = make_desc(sbase + OFF_WHI);
        const uint64_t dBlo = make_desc(sbase + OFF_WLO);
        const uint32_t offA[8] = {0, 2, 4, 6, 1024, 1026, 1028, 1030};
        const uint32_t offB[8] = {0, 2, 4, 6, 512, 514, 516, 518};

        float ysum[64];
#pragma unroll
        for (int c = 0; c < 64; c++) ysum[c] = 0.0f;

        for (int r = 0; r <= 16; r++) {
            // ---- issuer (warp 8 only) ----
            if (wid == 8 && r < 16) {
                const int b = r & 1;
                MBARRIER_WAIT_PARITY(mb_ufull + b * 8, (r >> 1) & 1);
                if (r >= 2) MBARRIER_WAIT_PARITY(mb_edone + b * 8, ((r - 2) >> 1) & 1);
                TCGEN05_FENCE_AFTER();
                if (elect_one()) {
                    const uint64_t dA = make_desc(sbase + b * 32768);
                    const uint32_t dst = tmem + b * 64;
#pragma unroll
                    for (int s = 0; s < 8; s++)
                        mma_tf32_ss(dst, dA + offA[s], dBhi + offB[s], IDESC_TF32, s > 0);
#pragma unroll
                    for (int s = 0; s < 8; s++)
                        mma_tf32_ss(dst, dA + offA[s], dBlo + offB[s], IDESC_TF32, true);
                    TCGEN05_COMMIT(mb_mdone + b * 8);
                }
            }
            // ---- epilogue for round r-1 ----
            if (r >= 1) {
                const int pr = r - 1;
                const int pb = pr & 1;
                MBARRIER_WAIT_PARITY(mb_mdone + pb * 8, (pr >> 1) & 1);
                TCGEN05_FENCE_AFTER();
                uint32_t tmp[32];
                TCGEN05_LD_32X32B_X32(tmp, tmem + pb * 64);
                TCGEN05_WAIT_LD();
#pragma unroll
                for (int c4 = 0; c4 < 8; c4++) {
                    const float4 b4 = *(const float4*)&sB2[c4 * 4];
                    ysum[c4 * 4 + 0] += fmaxf(__uint_as_float(tmp[c4 * 4 + 0]) + b4.x, 0.0f);
                    ysum[c4 * 4 + 1] += fmaxf(__uint_as_float(tmp[c4 * 4 + 1]) + b4.y, 0.0f);
                    ysum[c4 * 4 + 2] += fmaxf(__uint_as_float(tmp[c4 * 4 + 2]) + b4.z, 0.0f);
                    ysum[c4 * 4 + 3] += fmaxf(__uint_as_float(tmp[c4 * 4 + 3]) + b4.w, 0.0f);
                }
                TCGEN05_LD_32X32B_X32(tmp, tmem + pb * 64 + 32);
                TCGEN05_WAIT_LD();
#pragma unroll
                for (int c4 = 0; c4 < 8; c4++) {
                    const float4 b4 = *(const float4*)&sB2[32 + c4 * 4];
                    ysum[32 + c4 * 4 + 0] += fmaxf(__uint_as_float(tmp[c4 * 4 + 0]) + b4.x, 0.0f);
                    ysum[32 + c4 * 4 + 1] += fmaxf(__uint_as_float(tmp[c4 * 4 + 1]) + b4.y, 0.0f);
                    ysum[32 + c4 * 4 + 2] += fmaxf(__uint_as_float(tmp[c4 * 4 + 2]) + b4.z, 0.0f);
                    ysum[32 + c4 * 4 + 3] += fmaxf(__uint_as_float(tmp[c4 * 4 + 3]) + b4.w, 0.0f);
                }
                TCGEN05_FENCE_BEFORE();
                __syncwarp();
                if (lid == 0) MBARRIER_ARRIVE(mb_edone + pb * 8);
            }
        }

        // ---- cross-lane reduce over i-slots, write sRed ----
        const int sp = wid - 8;
        float* sRed = (float*)smem;   // [4 sp][16 jj][64 ch]
#pragma unroll
        for (int c4 = 0; c4 < 16; c4++) {
            float4 v;
            v.x = ysum[c4 * 4 + 0] + __shfl_xor_sync(0xFFFFFFFFu, ysum[c4 * 4 + 0], 16);
            v.y = ysum[c4 * 4 + 1] + __shfl_xor_sync(0xFFFFFFFFu, ysum[c4 * 4 + 1], 16);
            v.z = ysum[c4 * 4 + 2] + __shfl_xor_sync(0xFFFFFFFFu, ysum[c4 * 4 + 2], 16);
            v.w = ysum[c4 * 4 + 3] + __shfl_xor_sync(0xFFFFFFFFu, ysum[c4 * 4 + 3], 16);
            if (lid < 16) *(float4*)&sRed[(sp * 16 + lid) * 64 + c4 * 4] = v;
        }
    }

    __syncthreads();

    // final sum over 4 subpartitions, write partials (all 384 threads)
    {
        float* sRed = (float*)smem;
        for (int o = t; o < 1024; o += NTHR) {
            int jj = o >> 6, ch = o & 63;
            float s = sRed[(0 * 16 + jj) * 64 + ch] + sRed[(1 * 16 + jj) * 64 + ch] +
                      sRed[(2 * 16 + jj) * 64 + ch] + sRed[(3 * 16 + jj) * 64 + ch];
            g_ysum_part[(ic * NN + j0 + jj) * 64 + ch] = s;
        }
    }

    __syncthreads();
    if (t == 0) {
#pragma unroll
        for (int m = 0; m < 6; m++) MBARRIER_INVAL(sbase + OFF_MBAR + m * 8);
    }
    if (wid == 0) TCGEN05_DEALLOC(tmem, 128);

#else  // ---------- scalar fallback (family-PTX pass; never runs on sm_103a) ----------
    float* sW2 = (float*)(smem + OFF_WHI);     // [c][k] linear
    float* sU  = (float*)smem;                 // [k][16]
    float* sHi = (float*)(smem + OFF_FHI);
    float* sJ  = (float*)(smem + OFF_FJ);

    for (int idx = t; idx < 4096; idx += NTHR) sW2[idx] = W2[idx];
    if (t < 64) { swJ[t] = W1[t * 35 + 32]; sB2[t] = b2[t]; }
    for (int idx = t; idx < 1024; idx += NTHR)
        sHj[idx] = g_hj[(j0 + (idx >> 6)) * 64 + (idx & 63)];
    __syncthreads();

    const int jjf = (t < 256) ? (t >> 4) : 0;
    float acc[4] = {0.f, 0.f, 0.f, 0.f};
    for (int i = ic * 128; i < ic * 128 + 128; i++) {
        if (t < 64) sHi[t] = g_hi[i * 64 + t];
        if (t < 16) sJ[t] = J[i * NN + j0 + t];
        __syncthreads();
        if (t < 256) {
#pragma unroll
            for (int q = 0; q < 4; q++) {
                int idx = t * 4 + q;
                int k = idx >> 4, jl = idx & 15;
                float u = fmaf(sJ[jl], swJ[k], sHi[k] + sHj[jl * 64 + k]);
                sU[k * 16 + jl] = fmaxf(u, 0.0f);
            }
        }
        __syncthreads();
        if (t < 256) {
#pragma unroll
            for (int q = 0; q < 4; q++) {
                int ch = (t & 15) * 4 + q;
                float v = sB2[ch];
                for (int k = 0; k < 64; k++) v = fmaf(sW2[ch * 64 + k], sU[k * 16 + jjf], v);
                acc[q] += fmaxf(v, 0.0f);
            }
        }
        __syncthreads();
    }
    if (t < 256) {
#pragma unroll
        for (int q = 0; q < 4; q++) {
            int ch = (t & 15) * 4 + q;
            g_ysum_part[(ic * NN + j0 + jjf) * 64 + ch] = acc[q];
        }
    }
#endif
}

// ============================================================
// Fused m_j + GRU + next-step hi/hj (steps 0-3) or readout (step 4)
// grid 128, block 128 (4 nodes per block)
// ============================================================
__global__ void mj_gru_kernel(const float* __restrict__ W3, const float* __restrict__ b3,
                              const float* __restrict__ W_ih, const float* __restrict__ b_ih,
                              const float* __restrict__ W_hh, const float* __restrict__ b_hh,
                              const float* __restrict__ W1, const float* __restrict__ b1,
                              const float* __restrict__ bn,
                              const float* __restrict__ Wr1, const float* __restrict__ br1,
                              const float* __restrict__ Wr2, const float* __restrict__ br2,
                              const float* __restrict__ Wr3, const float* __restrict__ br3,
                              float* __restrict__ out, int step) {
    __shared__ float sY[4][64];
    __shared__ float sH[4][16], sMJ[4][32], sGI[4][48], sGH[4][48], sHn[4][16];
    __shared__ float sR2[4][64], sR3[4][2];
    const int t = threadIdx.x;
    const int n0 = blockIdx.x * 4;

    // reduce 4 partials: 4 nodes x 64 ch
#pragma unroll
    for (int q = 0; q < 2; q++) {
        int idx = t + q * 128;
        int jl = idx >> 6, k = idx & 63;
        float s = 0.0f;
#pragma unroll
        for (int p = 0; p < 4; p++) s += g_ysum_part[(p * NN + n0 + jl) * 64 + k];
        sY[jl][k] = s;
    }
    if (t < 64) { int nl = t >> 4, s = t & 15; sH[nl][s] = g_h[(n0 + nl) * 16 + s]; }
    __syncthreads();

    // m_j: 4 nodes x 32 ch = 128 threads
    {
        const int jl = t >> 5, c2 = t & 31;
        float s = 512.0f * b3[c2];
#pragma unroll
        for (int k = 0; k < 64; k++) s = fmaf(W3[c2 * 64 + k], sY[jl][k], s);
        sMJ[jl][c2] = s;
    }
    __syncthreads();

    // gates: 4 nodes x 48 = 192
#pragma unroll
    for (int q = 0; q < 2; q++) {
        int idx = t + q * 128;
        if (idx < 192) {
            int nl = idx / 48, g = idx % 48;
            float gi = b_ih[g], gh = b_hh[g];
#pragma unroll
            for (int s = 0; s < 16; s++) {
                gi = fmaf(sH[nl][s], W_ih[g * 48 + s], gi);
                gh = fmaf(sH[nl][s], W_hh[g * 16 + s], gh);
            }
#pragma unroll
            for (int m = 0; m < 32; m++) gi = fmaf(sMJ[nl][m], W_ih[g * 48 + 16 + m], gi);
            sGI[nl][g] = gi;
            sGH[nl][g] = gh;
        }
    }
    __syncthreads();

    if (t < 64) {
        int nl = t >> 4, s = t & 15;
        float r = sigmoidf(sGI[nl][s] + sGH[nl][s]);
        float z = sigmoidf(sGI[nl][16 + s] + sGH[nl][16 + s]);
        float nv = tanhf(sGI[nl][32 + s] + r * sGH[nl][32 + s]);
        float hn = (1.0f - z) * nv + z * sH[nl][s];
        sHn[nl][s] = hn;
        g_h[(n0 + nl) * 16 + s] = hn;
    }
    __syncthreads();

    if (step < 4) {
        // hi/hj for next step: 4 nodes x 64 c x {hi,hj} = 512 outputs
#pragma unroll
        for (int q = 0; q < 4; q++) {
            int idx = t + q * 128;
            int nl = idx >> 7, rem = idx & 127;
            int c = rem & 63, which = rem >> 6;
            int ng = n0 + nl;
            const float* w = &W1[c * 35 + (which ? 16 : 0)];
            float s = which ? fmaf(bn[ng], W1[c * 35 + 34], b1[c]) : bn[ng] * W1[c * 35 + 33];
#pragma unroll
            for (int sd = 0; sd < 16; sd++) s = fmaf(sHn[nl][sd], w[sd], s);
            if (which) g_hj[ng * 64 + c] = s;
            else       g_hi[ng * 64 + c] = s;
        }
    } else {
        // fused readout for these 4 nodes
#pragma unroll
        for (int q = 0; q < 2; q++) {
            int idx = t + q * 128;
            int nl = idx >> 6, o = idx & 63;
            float s = br1[o];
#pragma unroll
            for (int k = 0; k < 16; k++) s = fmaf(sHn[nl][k], Wr1[o * 16 + k], s);
            sY[nl][o] = fmaxf(s, 0.0f);
        }
        __syncthreads();
#pragma unroll
        for (int q = 0; q < 2; q++) {
            int idx = t + q * 128;
            int nl = idx >> 6, o = idx & 63;
            float s = br2[o];
#pragma unroll
            for (int k = 0; k < 64; k++) s = fmaf(sY[nl][k], Wr2[o * 64 + k], s);
            sR2[nl][o] = fmaxf(s, 0.0f);
        }
        __syncthreads();
        if (t < 8) {
            int nl = t >> 1, o = t & 1;
            float s = br3[o];
#pragma unroll
            for (int k = 0; k < 64; k++) s = fmaf(sR2[nl][k], Wr3[o * 64 + k], s);
            sR3[nl][o] = sigmoidf(s);
        }
        __syncthreads();
        if (t < 8) {
            int nl = t >> 1, o = t & 1;
            out[(n0 + nl) * 2 + o] = sR3[nl][o] / (sR3[nl][0] + sR3[nl][1]);
        }
    }
}

// ============================================================
extern "C" void kernel_launch(void* const* d_in, const int* in_sizes, int n_in,
                              void* d_out, int out_size) {
    const float* J    = (const float*)d_in[0];
    const float* b    = (const float*)d_in[1];
    const float* W1   = (const float*)d_in[2];
    const float* b1   = (const float*)d_in[3];
    const float* W2   = (const float*)d_in[4];
    const float* b2   = (const float*)d_in[5];
    const float* W3   = (const float*)d_in[6];
    const float* b3   = (const float*)d_in[7];
    const float* W_ih = (const float*)d_in[8];
    const float* b_ih = (const float*)d_in[9];
    const float* W_hh = (const float*)d_in[10];
    const float* b_hh = (const float*)d_in[11];
    const float* Wr1  = (const float*)d_in[12];
    const float* br1  = (const float*)d_in[13];
    const float* Wr2  = (const float*)d_in[14];
    const float* br2  = (const float*)d_in[15];
    const float* Wr3  = (const float*)d_in[16];
    const float* br3  = (const float*)d_in[17];
    float* out = (float*)d_out;

    cudaFuncSetAttribute(edge_tc_kernel, cudaFuncAttributeMaxDynamicSharedMemorySize, SMEM_EDGE);

    init_kernel<<<128, 256>>>(b, W1, b1);
    for (int step = 0; step < 5; step++) {
        edge_tc_kernel<<<dim3(32, 4), NTHR, SMEM_EDGE>>>(J, W1, W2, b2);
        mj_gru_kernel<<<128, 128>>>(W3, b3, W_ih, b_ih, W_hh, b_hh, W1, b1, b,
                                    Wr1, br1, Wr2, br2, Wr3, br3, out, step);
    }
}

// round 12
// speedup vs baseline: 1.2133x; 1.2133x over previous
#include <cuda_runtime.h>
#include <cstdint>
#include <math.h>

#define NN 512

#if defined(__CUDA_ARCH_FEAT_SM103_ALL) || defined(__CUDA_ARCH_FEAT_SM100_ALL)
#define HAS_TCGEN05 1
#else
#define HAS_TCGEN05 0
#endif

// ---------------- device scratch ----------------
__device__ float g_h[NN * 16];
__device__ float g_hi[NN * 64];
__device__ float g_hj[NN * 64];
__device__ float g_ysum_part[8 * NN * 64];

// ---------------- PTX helpers ----------------
__device__ __forceinline__ uint32_t smem_u32(const void* p) {
    uint32_t a;
    asm("{ .reg .u64 t; cvta.to.shared.u64 t, %1; cvt.u32.u64 %0, t; }" : "=r"(a) : "l"(p));
    return a;
}
__device__ __forceinline__ float tf32_rna(float x) {
    float r;
    asm("cvt.rna.tf32.f32 %0, %1;" : "=f"(r) : "f"(x));
    return r;
}
__device__ __forceinline__ uint32_t sw128(uint32_t b) { return b ^ ((b >> 3) & 0x70); }
__device__ __forceinline__ float sigmoidf(float x) { return 1.0f / (1.0f + expf(-x)); }

#if HAS_TCGEN05
// ---- packed f32x2 ----
__device__ __forceinline__ unsigned long long pk2(float lo, float hi) {
    unsigned long long r;
    asm("mov.b64 %0, {%1, %2};" : "=l"(r) : "f"(lo), "f"(hi));
    return r;
}
__device__ __forceinline__ unsigned long long add2(unsigned long long a, unsigned long long b) {
    unsigned long long r;
    asm("add.rn.f32x2 %0, %1, %2;" : "=l"(r) : "l"(a), "l"(b));
    return r;
}
__device__ __forceinline__ unsigned long long fma2v(unsigned long long a, unsigned long long b,
                                                   unsigned long long c) {
    unsigned long long r;
    asm("fma.rn.f32x2 %0, %1, %2, %3;" : "=l"(r) : "l"(a), "l"(b), "l"(c));
    return r;
}
__device__ __forceinline__ float2 upk2(unsigned long long v) {
    float2 f;
    asm("mov.b64 {%0, %1}, %2;" : "=f"(f.x), "=f"(f.y) : "l"(v));
    return f;
}

__device__ __forceinline__ uint32_t elect_one() {
    uint32_t p;
    asm volatile("{ .reg .pred p; elect.sync _|p, 0xFFFFFFFF; selp.b32 %0, 1, 0, p; }" : "=r"(p));
    return p;
}
#define MBARRIER_INIT(addr, cnt) \
    asm volatile("mbarrier.init.shared.b64 [%0], %1;" :: "r"((uint32_t)(addr)), "r"((uint32_t)(cnt)) : "memory")
#define MBARRIER_INVAL(addr) \
    asm volatile("mbarrier.inval.shared.b64 [%0];" :: "r"((uint32_t)(addr)) : "memory")
#define MBARRIER_ARRIVE(addr) \
    asm volatile("mbarrier.arrive.shared.b64 _, [%0];" :: "r"((uint32_t)(addr)) : "memory")
#define MBARRIER_WAIT_PARITY(mbar_smem_addr, phase_parity) do { \
    uint32_t _mbar = (uint32_t)(mbar_smem_addr); \
    uint32_t _parity = (uint32_t)(phase_parity); \
    uint32_t _done; \
    asm volatile( \
        "{\n\t.reg .pred p;\n\t" \
        "mbarrier.try_wait.parity.acquire.cta.shared::cta.b64 p, [%1], %2;\n\t" \
        "selp.b32 %0, 1, 0, p;\n\t}" \
        : "=r"(_done) : "r"(_mbar), "r"(_parity) : "memory"); \
    if (!_done) { \
        asm volatile( \
            "{\n\t.reg .pred P1;\n\t" \
            "WAIT_LOOP_%=:\n\t" \
            "mbarrier.try_wait.parity.acquire.cta.shared::cta.b64 P1, [%0], %1, 0x989680;\n\t" \
            "@P1 bra.uni WAIT_DONE_%=;\n\t" \
            "bra.uni WAIT_LOOP_%=;\n\t" \
            "WAIT_DONE_%=:\n\t}" \
            :: "r"(_mbar), "r"(_parity) : "memory"); \
    } \
} while(0)
#define TCGEN05_ALLOC(saddr, ncols) \
    asm volatile("tcgen05.alloc.cta_group::1.sync.aligned.shared::cta.b32 [%0], %1;" \
                 :: "r"((uint32_t)(saddr)), "r"((uint32_t)(ncols)) : "memory")
#define TCGEN05_DEALLOC(taddr, ncols) \
    asm volatile("tcgen05.dealloc.cta_group::1.sync.aligned.b32 %0, %1;" :: "r"(taddr), "r"((uint32_t)(ncols)))
#define TCGEN05_RELINQ() \
    asm volatile("tcgen05.relinquish_alloc_permit.cta_group::1.sync.aligned;")
#define TCGEN05_COMMIT(mbar) \
    asm volatile("tcgen05.commit.cta_group::1.mbarrier::arrive::one.shared::cluster.b64 [%0];" \
                 :: "r"((uint32_t)(mbar)) : "memory")
#define TCGEN05_FENCE_AFTER()  asm volatile("tcgen05.fence::after_thread_sync;" ::: "memory")
#define TCGEN05_FENCE_BEFORE() asm volatile("tcgen05.fence::before_thread_sync;" ::: "memory")
#define TCGEN05_WAIT_LD()      asm volatile("tcgen05.wait::ld.sync.aligned;" ::: "memory")
#define FENCE_PROXY_ASYNC()    asm volatile("fence.proxy.async.shared::cta;" ::: "memory")

#define TCGEN05_LD_32X32B_X32(r, tmem_addr) \
    asm volatile( \
        "tcgen05.ld.sync.aligned.32x32b.x32.b32 " \
        "{%0, %1, %2, %3, %4, %5, %6, %7, " \
        " %8, %9, %10, %11, %12, %13, %14, %15, " \
        " %16, %17, %18, %19, %20, %21, %22, %23, " \
        " %24, %25, %26, %27, %28, %29, %30, %31}, [%32];" \
        : "=r"((r)[0]),  "=r"((r)[1]),  "=r"((r)[2]),  "=r"((r)[3]), \
          "=r"((r)[4]),  "=r"((r)[5]),  "=r"((r)[6]),  "=r"((r)[7]), \
          "=r"((r)[8]),  "=r"((r)[9]),  "=r"((r)[10]), "=r"((r)[11]), \
          "=r"((r)[12]), "=r"((r)[13]), "=r"((r)[14]), "=r"((r)[15]), \
          "=r"((r)[16]), "=r"((r)[17]), "=r"((r)[18]), "=r"((r)[19]), \
          "=r"((r)[20]), "=r"((r)[21]), "=r"((r)[22]), "=r"((r)[23]), \
          "=r"((r)[24]), "=r"((r)[25]), "=r"((r)[26]), "=r"((r)[27]), \
          "=r"((r)[28]), "=r"((r)[29]), "=r"((r)[30]), "=r"((r)[31]) \
        : "r"(tmem_addr))

// SMEM descriptor: SW128, Blackwell (version=1), SBO=64, LBO=1
static __device__ __forceinline__ uint64_t make_desc(uint32_t addr) {
    const uint64_t base = (uint64_t(2) << 61) | (uint64_t(1) << 46) |
                          (uint64_t(64) << 32) | (uint64_t(1) << 16);
    return base | ((uint64_t)(addr >> 4) & 0x3FFF);
}

// tcgen05.mma kind::tf32, SS, cta_group::1
__device__ __forceinline__ void mma_tf32_ss(uint32_t d, uint64_t ad, uint64_t bd,
                                            uint32_t idesc, bool acc) {
    uint32_t en = acc ? 1u : 0u;
    asm volatile(
        "{\n\t.reg .pred p;\n\t"
        "setp.ne.u32 p, %5, 0;\n\t"
        "tcgen05.mma.cta_group::1.kind::tf32 [%0], %1, %2, %3, {%4, %4, %4, %4}, p;\n\t}"
        :: "r"(d), "l"(ad), "l"(bd), "r"(idesc), "r"(0u), "r"(en) : "memory");
}

// idesc: c=F32(1@[4]), a=TF32(2@[7]), b=TF32(2@[10]), N=64 (8@[17]), M=128 (8@[24])
#define IDESC_TF32 ((1u << 4) | (2u << 7) | (2u << 10) | (8u << 17) | (8u << 24))
#endif  // HAS_TCGEN05

// ---------------- SMEM layout (edge kernel, dynamic) ----------------
// Double-buffered U: bank b at b*32768 (32 KB each)
#define OFF_WHI  65536       // 64x64 f32 swizzled (16384)
#define OFF_WLO  81920
#define OFF_HJ   98304       // 16x64 f32 (4096)
#define OFF_WJ   102400      // 64 f32
#define OFF_B2   102656      // 64 f32
#define OFF_TPTR 102912
#define OFF_MBAR 102928      // 6 mbarriers: ufull[2], mdone[2], edone[2]
#define SMEM_EDGE 102976
// fallback-only offsets (reuse U buffer space)
#define OFF_FHI  32768
#define OFF_FJ   33792

// ============================================================
// Init: h0 = 0; hi/hj terms for h=0
// ============================================================
__global__ void init_kernel(const float* __restrict__ b, const float* __restrict__ W1,
                            const float* __restrict__ b1) {
    int idx = blockIdx.x * 256 + threadIdx.x;
    int node = idx >> 6, c = idx & 63;
    g_hi[idx] = b[node] * W1[c * 35 + 33];
    g_hj[idx] = fmaf(b[node], W1[c * 35 + 34], b1[c]);
    if (c < 16) g_h[node * 16 + c] = 0.0f;
}

// ============================================================
// Edge kernel: warp-specialized tcgen05 tf32 (2-pass W split)
//   warps 0-3: U producers (2 i-rows each), packed f32x2 math
//   warps 4-7: per-subpartition consumers; warp 4 issues MMAs.
// grid (32 j-tiles, 8 i-chunks), block 256, 2 CTAs/SM
// PDL: W2 staging before griddepsync; trigger after partial writes.
// ============================================================
__global__ __launch_bounds__(256, 2) void edge_tc_kernel(const float* __restrict__ J,
                                                         const float* __restrict__ W1,
                                                         const float* __restrict__ W2,
                                                         const float* __restrict__ b2) {
    extern __shared__ __align__(1024) char smem[];
    const int t = threadIdx.x;
    const int jt = blockIdx.x, ic = blockIdx.y;
    const int j0 = jt * 16;

    float* sHj = (float*)(smem + OFF_HJ);
    float* swJ = (float*)(smem + OFF_WJ);
    float* sB2 = (float*)(smem + OFF_B2);

#if HAS_TCGEN05
    const uint32_t sbase = smem_u32(smem);
    const int wid = t >> 5, lid = t & 31;

    if (wid == 0) {
        TCGEN05_ALLOC(sbase + OFF_TPTR, 128);
        TCGEN05_RELINQ();
    }
    if (t == 0) {
        MBARRIER_INIT(sbase + OFF_MBAR + 0, 4);   // ufull[0]
        MBARRIER_INIT(sbase + OFF_MBAR + 8, 4);   // ufull[1]
        MBARRIER_INIT(sbase + OFF_MBAR + 16, 1);  // mdone[0]
        MBARRIER_INIT(sbase + OFF_MBAR + 24, 1);  // mdone[1]
        MBARRIER_INIT(sbase + OFF_MBAR + 32, 4);  // edone[0]
        MBARRIER_INIT(sbase + OFF_MBAR + 40, 4);  // edone[1]
    }

    // stage W2 hi/lo (inputs only — runs BEFORE the PDL dependency sync)
#pragma unroll
    for (int q = 0; q < 16; q++) {
        int idx = t + q * 256;
        int c = idx >> 6, k = idx & 63;
        float w = W2[c * 64 + k];
        float whi = tf32_rna(w);
        float wlo = w - whi;
        uint32_t byte = (((c >> 3) + ((k >> 5) << 3)) << 10) + ((c & 7) << 7) + ((k & 31) << 2);
        byte = sw128(byte);
        *(float*)(smem + OFF_WHI + byte) = whi;
        *(float*)(smem + OFF_WLO + byte) = wlo;
    }
    if (t < 64) { swJ[t] = W1[t * 35 + 32]; sB2[t] = b2[t]; }

    // wait for upstream kernel (mj_gru / init) results before touching g_hj / g_hi
    cudaGridDependencySynchronize();

#pragma unroll
    for (int q = 0; q < 4; q++) {
        int idx = t + q * 256;
        sHj[idx] = g_hj[(j0 + (idx >> 6)) * 64 + (idx & 63)];
    }
    FENCE_PROXY_ASYNC();
    __syncthreads();

    const uint32_t tmem = *(volatile uint32_t*)(smem + OFF_TPTR);
    const uint32_t mb_ufull = sbase + OFF_MBAR;
    const uint32_t mb_mdone = sbase + OFF_MBAR + 16;
    const uint32_t mb_edone = sbase + OFF_MBAR + 32;

    if (wid < 4) {
        // ================= producer warps (packed f32x2) =================
        const int k0 = (lid & 15) * 4;
        const unsigned long long wq2a = pk2(swJ[k0], swJ[k0 + 1]);
        const unsigned long long wq2b = pk2(swJ[k0 + 2], swJ[k0 + 3]);
        const uint32_t kpart = ((uint32_t)(k0 >> 5) << 14) + ((k0 & 31) << 2);
        const int ii = lid >> 4;
        const int ebase = (2 * wid + ii) * 16;
        const int ibase = ic * 64;

        float4 hv = *(const float4*)&g_hi[(ibase + 2 * wid + ii) * 64 + k0];
        float jp = J[(ibase + 2 * wid + ii) * NN + j0 + (lid & 15)];

        for (int r = 0; r < 8; r++) {
            const int b = r & 1;
            if (r >= 2) MBARRIER_WAIT_PARITY(mb_mdone + b * 8, ((r - 2) >> 1) & 1);
            char* ubase = smem + b * 32768;
            const unsigned long long hv2a = pk2(hv.x, hv.y);
            const unsigned long long hv2b = pk2(hv.z, hv.w);
#pragma unroll
            for (int m = 0; m < 16; m++) {
                const float Jv = __shfl_sync(0xFFFFFFFFu, jp, (lid & 16) + m);
                const ulonglong2 hj2 = *(const ulonglong2*)&sHj[m * 64 + k0];
                const unsigned long long jv2 = pk2(Jv, Jv);
                unsigned long long t0 = fma2v(jv2, wq2a, add2(hv2a, hj2.x));
                unsigned long long t1 = fma2v(jv2, wq2b, add2(hv2b, hj2.y));
                const float2 a = upk2(t0);
                const float2 c = upk2(t1);
                const int e = ebase + m;
                float4 u;
                u.x = fmaxf(a.x, 0.0f);
                u.y = fmaxf(a.y, 0.0f);
                u.z = fmaxf(c.x, 0.0f);
                u.w = fmaxf(c.y, 0.0f);
                uint32_t byte = ((uint32_t)(e >> 3) << 10) + ((e & 7) << 7) + kpart;
                byte = sw128(byte);
                *(float4*)(ubase + byte) = u;
            }
            float4 hn = make_float4(0.f, 0.f, 0.f, 0.f);
            float jn = 0.f;
            if (r < 7) {
                const int i0n = ibase + (r + 1) * 8 + 2 * wid + ii;
                hn = *(const float4*)&g_hi[i0n * 64 + k0];
                jn = J[i0n * NN + j0 + (lid & 15)];
            }
            FENCE_PROXY_ASYNC();
            __syncwarp();
            if (lid == 0) MBARRIER_ARRIVE(mb_ufull + b * 8);
            hv = hn; jp = jn;
        }
    } else {
        // ================= consumer warps (wid 4-7) =================
        const uint64_t dBhi = make_desc(sbase + OFF_WHI);
        const uint64_t dBlo = make_desc(sbase + OFF_WLO);
        const uint32_t offA[8] = {0, 2, 4, 6, 1024, 1026, 1028, 1030};
        const uint32_t offB[8] = {0, 2, 4, 6, 512, 514, 516, 518};

        float ysum[64];
#pragma unroll
        for (int c = 0; c < 64; c++) ysum[c] = 0.0f;

        for (int r = 0; r <= 8; r++) {
            // ---- issuer (warp 4 only) ----
            if (wid == 4 && r < 8) {
                const int b = r & 1;
                MBARRIER_WAIT_PARITY(mb_ufull + b * 8, (r >> 1) & 1);
                if (r >= 2) MBARRIER_WAIT_PARITY(mb_edone + b * 8, ((r - 2) >> 1) & 1);
                TCGEN05_FENCE_AFTER();
                if (elect_one()) {
                    const uint64_t dA = make_desc(sbase + b * 32768);
                    const uint32_t dst = tmem + b * 64;
#pragma unroll
                    for (int s = 0; s < 8; s++)
                        mma_tf32_ss(dst, dA + offA[s], dBhi + offB[s], IDESC_TF32, s > 0);
#pragma unroll
                    for (int s = 0; s < 8; s++)
                        mma_tf32_ss(dst, dA + offA[s], dBlo + offB[s], IDESC_TF32, true);
                    TCGEN05_COMMIT(mb_mdone + b * 8);
                }
            }
            // ---- epilogue for round r-1 ----
            if (r >= 1) {
                const int pr = r - 1;
                const int pb = pr & 1;
                MBARRIER_WAIT_PARITY(mb_mdone + pb * 8, (pr >> 1) & 1);
                TCGEN05_FENCE_AFTER();
                uint32_t tmp[32];
                TCGEN05_LD_32X32B_X32(tmp, tmem + pb * 64);
                TCGEN05_WAIT_LD();
#pragma unroll
                for (int c4 = 0; c4 < 8; c4++) {
                    const float4 b4 = *(const float4*)&sB2[c4 * 4];
                    ysum[c4 * 4 + 0] += fmaxf(__uint_as_float(tmp[c4 * 4 + 0]) + b4.x, 0.0f);
                    ysum[c4 * 4 + 1] += fmaxf(__uint_as_float(tmp[c4 * 4 + 1]) + b4.y, 0.0f);
                    ysum[c4 * 4 + 2] += fmaxf(__uint_as_float(tmp[c4 * 4 + 2]) + b4.z, 0.0f);
                    ysum[c4 * 4 + 3] += fmaxf(__uint_as_float(tmp[c4 * 4 + 3]) + b4.w, 0.0f);
                }
                TCGEN05_LD_32X32B_X32(tmp, tmem + pb * 64 + 32);
                TCGEN05_WAIT_LD();
#pragma unroll
                for (int c4 = 0; c4 < 8; c4++) {
                    const float4 b4 = *(const float4*)&sB2[32 + c4 * 4];
                    ysum[32 + c4 * 4 + 0] += fmaxf(__uint_as_float(tmp[c4 * 4 + 0]) + b4.x, 0.0f);
                    ysum[32 + c4 * 4 + 1] += fmaxf(__uint_as_float(tmp[c4 * 4 + 1]) + b4.y, 0.0f);
                    ysum[32 + c4 * 4 + 2] += fmaxf(__uint_as_float(tmp[c4 * 4 + 2]) + b4.z, 0.0f);
                    ysum[32 + c4 * 4 + 3] += fmaxf(__uint_as_float(tmp[c4 * 4 + 3]) + b4.w, 0.0f);
                }
                TCGEN05_FENCE_BEFORE();
                __syncwarp();
                if (lid == 0) MBARRIER_ARRIVE(mb_edone + pb * 8);
            }
        }

        // ---- cross-lane reduce over i-slots, write sRed ----
        const int sp = wid & 3;
        float* sRed = (float*)smem;   // [4 sp][16 jj][64 ch]
#pragma unroll
        for (int c4 = 0; c4 < 16; c4++) {
            float4 v;
            v.x = ysum[c4 * 4 + 0] + __shfl_xor_sync(0xFFFFFFFFu, ysum[c4 * 4 + 0], 16);
            v.y = ysum[c4 * 4 + 1] + __shfl_xor_sync(0xFFFFFFFFu, ysum[c4 * 4 + 1], 16);
            v.z = ysum[c4 * 4 + 2] + __shfl_xor_sync(0xFFFFFFFFu, ysum[c4 * 4 + 2], 16);
            v.w = ysum[c4 * 4 + 3] + __shfl_xor_sync(0xFFFFFFFFu, ysum[c4 * 4 + 3], 16);
            if (lid < 16) *(float4*)&sRed[(sp * 16 + lid) * 64 + c4 * 4] = v;
        }
    }

    __syncthreads();

    // final sum over 4 subpartitions, write partials (all 256 threads)
    {
        float* sRed = (float*)smem;
#pragma unroll
        for (int q = 0; q < 4; q++) {
            int o = t * 4 + q;
            int jj = o >> 6, ch = o & 63;
            float s = sRed[(0 * 16 + jj) * 64 + ch] + sRed[(1 * 16 + jj) * 64 + ch] +
                      sRed[(2 * 16 + jj) * 64 + ch] + sRed[(3 * 16 + jj) * 64 + ch];
            g_ysum_part[(ic * NN + j0 + jj) * 64 + ch] = s;
        }
    }

    __syncthreads();
    // all global writes done — allow dependent kernel to launch
    cudaTriggerProgrammaticLaunchCompletion();

    if (t == 0) {
#pragma unroll
        for (int m = 0; m < 6; m++) MBARRIER_INVAL(sbase + OFF_MBAR + m * 8);
    }
    if (wid == 0) TCGEN05_DEALLOC(tmem, 128);

#else  // ---------- scalar fallback (family-PTX pass; never runs on sm_103a) ----------
    float* sW2 = (float*)(smem + OFF_WHI);     // [c][k] linear
    float* sU  = (float*)smem;                 // [k][16]
    float* sHi = (float*)(smem + OFF_FHI);
    float* sJ  = (float*)(smem + OFF_FJ);

#pragma unroll
    for (int q = 0; q < 16; q++) {
        int idx = t + q * 256;
        sW2[idx] = W2[idx];
    }
    if (t < 64) { swJ[t] = W1[t * 35 + 32]; sB2[t] = b2[t]; }
    cudaGridDependencySynchronize();
#pragma unroll
    for (int q = 0; q < 4; q++) {
        int idx = t + q * 256;
        sHj[idx] = g_hj[(j0 + (idx >> 6)) * 64 + (idx & 63)];
    }
    __syncthreads();

    const int jjf = t >> 4;
    float acc[4] = {0.f, 0.f, 0.f, 0.f};
    for (int i = ic * 64; i < ic * 64 + 64; i++) {
        if (t < 64) sHi[t] = g_hi[i * 64 + t];
        if (t < 16) sJ[t] = J[i * NN + j0 + t];
        __syncthreads();
#pragma unroll
        for (int q = 0; q < 4; q++) {
            int idx = t * 4 + q;
            int k = idx >> 4, jl = idx & 15;
            float u = fmaf(sJ[jl], swJ[k], sHi[k] + sHj[jl * 64 + k]);
            sU[k * 16 + jl] = fmaxf(u, 0.0f);
        }
        __syncthreads();
#pragma unroll
        for (int q = 0; q < 4; q++) {
            int ch = (t & 15) * 4 + q;
            float v = sB2[ch];
            for (int k = 0; k < 64; k++) v = fmaf(sW2[ch * 64 + k], sU[k * 16 + jjf], v);
            acc[q] += fmaxf(v, 0.0f);
        }
        __syncthreads();
    }
#pragma unroll
    for (int q = 0; q < 4; q++) {
        int ch = (t & 15) * 4 + q;
        g_ysum_part[(ic * NN + j0 + jjf) * 64 + ch] = acc[q];
    }
    cudaTriggerProgrammaticLaunchCompletion();
#endif
}

// ============================================================
// Fused m_j + GRU + next-step hi/hj (steps 0-3) or readout (step 4)
// grid 128, block 128 (4 nodes per block)
// ============================================================
__global__ void mj_gru_kernel(const float* __restrict__ W3, const float* __restrict__ b3,
                              const float* __restrict__ W_ih, const float* __restrict__ b_ih,
                              const float* __restrict__ W_hh, const float* __restrict__ b_hh,
                              const float* __restrict__ W1, const float* __restrict__ b1,
                              const float* __restrict__ bn,
                              const float* __restrict__ Wr1, const float* __restrict__ br1,
                              const float* __restrict__ Wr2, const float* __restrict__ br2,
                              const float* __restrict__ Wr3, const float* __restrict__ br3,
                              float* __restrict__ out, int step) {
    __shared__ float sY[4][64];
    __shared__ float sH[4][16], sMJ[4][32], sGI[4][48], sGH[4][48], sHn[4][16];
    __shared__ float sR2[4][64], sR3[4][2];
    const int t = threadIdx.x;
    const int n0 = blockIdx.x * 4;

    cudaGridDependencySynchronize();

    // reduce 8 partials: 4 nodes x 64 ch
#pragma unroll
    for (int q = 0; q < 2; q++) {
        int idx = t + q * 128;
        int jl = idx >> 6, k = idx & 63;
        float s = 0.0f;
#pragma unroll
        for (int p = 0; p < 8; p++) s += g_ysum_part[(p * NN + n0 + jl) * 64 + k];
        sY[jl][k] = s;
    }
    if (t < 64) { int nl = t >> 4, s = t & 15; sH[nl][s] = g_h[(n0 + nl) * 16 + s]; }
    __syncthreads();

    // m_j: 4 nodes x 32 ch = 128 threads
    {
        const int jl = t >> 5, c2 = t & 31;
        float s = 512.0f * b3[c2];
#pragma unroll
        for (int k = 0; k < 64; k++) s = fmaf(W3[c2 * 64 + k], sY[jl][k], s);
        sMJ[jl][c2] = s;
    }
    __syncthreads();

    // gates: 4 nodes x 48 = 192
#pragma unroll
    for (int q = 0; q < 2; q++) {
        int idx = t + q * 128;
        if (idx < 192) {
            int nl = idx / 48, g = idx % 48;
            float gi = b_ih[g], gh = b_hh[g];
#pragma unroll
            for (int s = 0; s < 16; s++) {
                gi = fmaf(sH[nl][s], W_ih[g * 48 + s], gi);
                gh = fmaf(sH[nl][s], W_hh[g * 16 + s], gh);
            }
#pragma unroll
            for (int m = 0; m < 32; m++) gi = fmaf(sMJ[nl][m], W_ih[g * 48 + 16 + m], gi);
            sGI[nl][g] = gi;
            sGH[nl][g] = gh;
        }
    }
    __syncthreads();

    if (t < 64) {
        int nl = t >> 4, s = t & 15;
        float r = sigmoidf(sGI[nl][s] + sGH[nl][s]);
        float z = sigmoidf(sGI[nl][16 + s] + sGH[nl][16 + s]);
        float nv = tanhf(sGI[nl][32 + s] + r * sGH[nl][32 + s]);
        float hn = (1.0f - z) * nv + z * sH[nl][s];
        sHn[nl][s] = hn;
        g_h[(n0 + nl) * 16 + s] = hn;
    }
    __syncthreads();

    if (step < 4) {
        // hi/hj for next step: 4 nodes x 64 c x {hi,hj} = 512 outputs
#pragma unroll
        for (int q = 0; q < 4; q++) {
            int idx = t + q * 128;
            int nl = idx >> 7, rem = idx & 127;
            int c = rem & 63, which = rem >> 6;
            int ng = n0 + nl;
            const float* w = &W1[c * 35 + (which ? 16 : 0)];
            float s = which ? fmaf(bn[ng], W1[c * 35 + 34], b1[c]) : bn[ng] * W1[c * 35 + 33];
#pragma unroll
            for (int sd = 0; sd < 16; sd++) s = fmaf(sHn[nl][sd], w[sd], s);
            if (which) g_hj[ng * 64 + c] = s;
            else       g_hi[ng * 64 + c] = s;
        }
    } else {
        // fused readout for these 4 nodes
#pragma unroll
        for (int q = 0; q < 2; q++) {
            int idx = t + q * 128;
            int nl = idx >> 6, o = idx & 63;
            float s = br1[o];
#pragma unroll
            for (int k = 0; k < 16; k++) s = fmaf(sHn[nl][k], Wr1[o * 16 + k], s);
            sY[nl][o] = fmaxf(s, 0.0f);
        }
        __syncthreads();
#pragma unroll
        for (int q = 0; q < 2; q++) {
            int idx = t + q * 128;
            int nl = idx >> 6, o = idx & 63;
            float s = br2[o];
#pragma unroll
            for (int k = 0; k < 64; k++) s = fmaf(sY[nl][k], Wr2[o * 64 + k], s);
            sR2[nl][o] = fmaxf(s, 0.0f);
        }
        __syncthreads();
        if (t < 8) {
            int nl = t >> 1, o = t & 1;
            float s = br3[o];
#pragma unroll
            for (int k = 0; k < 64; k++) s = fmaf(sR2[nl][k], Wr3[o * 64 + k], s);
            sR3[nl][o] = sigmoidf(s);
        }
        __syncthreads();
        if (t < 8) {
            int nl = t >> 1, o = t & 1;
            out[(n0 + nl) * 2 + o] = sR3[nl][o] / (sR3[nl][0] + sR3[nl][1]);
        }
    }
}

// ============================================================
// host-side PDL launch helper
// ============================================================
static inline void launch_pdl(const void* func, dim3 grid, dim3 block, size_t smem,
                              void** args) {
    cudaLaunchConfig_t cfg = {};
    cfg.gridDim = grid;
    cfg.blockDim = block;
    cfg.dynamicSmemBytes = smem;
    cfg.stream = 0;
    cudaLaunchAttribute attr[1];
    attr[0].id = cudaLaunchAttributeProgrammaticStreamSerialization;
    attr[0].val.programmaticStreamSerializationAllowed = 1;
    cfg.attrs = attr;
    cfg.numAttrs = 1;
    cudaLaunchKernelExC(&cfg, func, args);
}

// ============================================================
extern "C" void kernel_launch(void* const* d_in, const int* in_sizes, int n_in,
                              void* d_out, int out_size) {
    const float* J    = (const float*)d_in[0];
    const float* b    = (const float*)d_in[1];
    const float* W1   = (const float*)d_in[2];
    const float* b1   = (const float*)d_in[3];
    const float* W2   = (const float*)d_in[4];
    const float* b2   = (const float*)d_in[5];
    const float* W3   = (const float*)d_in[6];
    const float* b3   = (const float*)d_in[7];
    const float* W_ih = (const float*)d_in[8];
    const float* b_ih = (const float*)d_in[9];
    const float* W_hh = (const float*)d_in[10];
    const float* b_hh = (const float*)d_in[11];
    const float* Wr1  = (const float*)d_in[12];
    const float* br1  = (const float*)d_in[13];
    const float* Wr2  = (const float*)d_in[14];
    const float* br2  = (const float*)d_in[15];
    const float* Wr3  = (const float*)d_in[16];
    const float* br3  = (const float*)d_in[17];
    float* out = (float*)d_out;

    cudaFuncSetAttribute(edge_tc_kernel, cudaFuncAttributeMaxDynamicSharedMemorySize, SMEM_EDGE);

    init_kernel<<<128, 256>>>(b, W1, b1);
    for (int step = 0; step < 5; step++) {
        {
            void* args[] = {(void*)&J, (void*)&W1, (void*)&W2, (void*)&b2};
            launch_pdl((const void*)edge_tc_kernel, dim3(32, 8), dim3(256), SMEM_EDGE, args);
        }
        {
            void* args[] = {(void*)&W3, (void*)&b3, (void*)&W_ih, (void*)&b_ih,
                            (void*)&W_hh, (void*)&b_hh, (void*)&W1, (void*)&b1,
                            (void*)&b, (void*)&Wr1, (void*)&br1, (void*)&Wr2,
                            (void*)&br2, (void*)&Wr3, (void*)&br3, (void*)&out,
                            (void*)&step};
            launch_pdl((const void*)mj_gru_kernel, dim3(128), dim3(128), 0, args);
        }
    }
}

// round 13
// speedup vs baseline: 1.3063x; 1.0766x over previous
#include <cuda_runtime.h>
#include <cstdint>
#include <math.h>

#define NN 512

#if defined(__CUDA_ARCH_FEAT_SM103_ALL) || defined(__CUDA_ARCH_FEAT_SM100_ALL)
#define HAS_TCGEN05 1
#else
#define HAS_TCGEN05 0
#endif

// ---------------- device scratch ----------------
__device__ float g_h[NN * 16];
__device__ float g_hi[NN * 64];
__device__ float g_hj[NN * 64];
__device__ float g_ysum_part[8 * NN * 64];

// ---------------- PTX helpers ----------------
__device__ __forceinline__ uint32_t smem_u32(const void* p) {
    uint32_t a;
    asm("{ .reg .u64 t; cvta.to.shared.u64 t, %1; cvt.u32.u64 %0, t; }" : "=r"(a) : "l"(p));
    return a;
}
__device__ __forceinline__ float tf32_rna(float x) {
    float r;
    asm("cvt.rna.tf32.f32 %0, %1;" : "=f"(r) : "f"(x));
    return r;
}
__device__ __forceinline__ uint32_t sw128(uint32_t b) { return b ^ ((b >> 3) & 0x70); }
__device__ __forceinline__ float sigmoidf(float x) { return 1.0f / (1.0f + expf(-x)); }

#if HAS_TCGEN05
// ---- packed f32x2 ----
__device__ __forceinline__ unsigned long long pk2(float lo, float hi) {
    unsigned long long r;
    asm("mov.b64 %0, {%1, %2};" : "=l"(r) : "f"(lo), "f"(hi));
    return r;
}
__device__ __forceinline__ unsigned long long add2(unsigned long long a, unsigned long long b) {
    unsigned long long r;
    asm("add.rn.f32x2 %0, %1, %2;" : "=l"(r) : "l"(a), "l"(b));
    return r;
}
__device__ __forceinline__ unsigned long long fma2v(unsigned long long a, unsigned long long b,
                                                   unsigned long long c) {
    unsigned long long r;
    asm("fma.rn.f32x2 %0, %1, %2, %3;" : "=l"(r) : "l"(a), "l"(b), "l"(c));
    return r;
}
__device__ __forceinline__ float2 upk2(unsigned long long v) {
    float2 f;
    asm("mov.b64 {%0, %1}, %2;" : "=f"(f.x), "=f"(f.y) : "l"(v));
    return f;
}

__device__ __forceinline__ uint32_t elect_one() {
    uint32_t p;
    asm volatile("{ .reg .pred p; elect.sync _|p, 0xFFFFFFFF; selp.b32 %0, 1, 0, p; }" : "=r"(p));
    return p;
}
#define MBARRIER_INIT(addr, cnt) \
    asm volatile("mbarrier.init.shared.b64 [%0], %1;" :: "r"((uint32_t)(addr)), "r"((uint32_t)(cnt)) : "memory")
#define MBARRIER_INVAL(addr) \
    asm volatile("mbarrier.inval.shared.b64 [%0];" :: "r"((uint32_t)(addr)) : "memory")
#define MBARRIER_ARRIVE(addr) \
    asm volatile("mbarrier.arrive.shared.b64 _, [%0];" :: "r"((uint32_t)(addr)) : "memory")
#define MBARRIER_WAIT_PARITY(mbar_smem_addr, phase_parity) do { \
    uint32_t _mbar = (uint32_t)(mbar_smem_addr); \
    uint32_t _parity = (uint32_t)(phase_parity); \
    uint32_t _done; \
    asm volatile( \
        "{\n\t.reg .pred p;\n\t" \
        "mbarrier.try_wait.parity.acquire.cta.shared::cta.b64 p, [%1], %2;\n\t" \
        "selp.b32 %0, 1, 0, p;\n\t}" \
        : "=r"(_done) : "r"(_mbar), "r"(_parity) : "memory"); \
    if (!_done) { \
        asm volatile( \
            "{\n\t.reg .pred P1;\n\t" \
            "WAIT_LOOP_%=:\n\t" \
            "mbarrier.try_wait.parity.acquire.cta.shared::cta.b64 P1, [%0], %1, 0x989680;\n\t" \
            "@P1 bra.uni WAIT_DONE_%=;\n\t" \
            "bra.uni WAIT_LOOP_%=;\n\t" \
            "WAIT_DONE_%=:\n\t}" \
            :: "r"(_mbar), "r"(_parity) : "memory"); \
    } \
} while(0)
#define TCGEN05_ALLOC(saddr, ncols) \
    asm volatile("tcgen05.alloc.cta_group::1.sync.aligned.shared::cta.b32 [%0], %1;" \
                 :: "r"((uint32_t)(saddr)), "r"((uint32_t)(ncols)) : "memory")
#define TCGEN05_DEALLOC(taddr, ncols) \
    asm volatile("tcgen05.dealloc.cta_group::1.sync.aligned.b32 %0, %1;" :: "r"(taddr), "r"((uint32_t)(ncols)))
#define TCGEN05_RELINQ() \
    asm volatile("tcgen05.relinquish_alloc_permit.cta_group::1.sync.aligned;")
#define TCGEN05_COMMIT(mbar) \
    asm volatile("tcgen05.commit.cta_group::1.mbarrier::arrive::one.shared::cluster.b64 [%0];" \
                 :: "r"((uint32_t)(mbar)) : "memory")
#define TCGEN05_FENCE_AFTER()  asm volatile("tcgen05.fence::after_thread_sync;" ::: "memory")
#define TCGEN05_FENCE_BEFORE() asm volatile("tcgen05.fence::before_thread_sync;" ::: "memory")
#define TCGEN05_WAIT_LD()      asm volatile("tcgen05.wait::ld.sync.aligned;" ::: "memory")
#define FENCE_PROXY_ASYNC()    asm volatile("fence.proxy.async.shared::cta;" ::: "memory")

#define TCGEN05_LD_32X32B_X32(r, tmem_addr) \
    asm volatile( \
        "tcgen05.ld.sync.aligned.32x32b.x32.b32 " \
        "{%0, %1, %2, %3, %4, %5, %6, %7, " \
        " %8, %9, %10, %11, %12, %13, %14, %15, " \
        " %16, %17, %18, %19, %20, %21, %22, %23, " \
        " %24, %25, %26, %27, %28, %29, %30, %31}, [%32];" \
        : "=r"((r)[0]),  "=r"((r)[1]),  "=r"((r)[2]),  "=r"((r)[3]), \
          "=r"((r)[4]),  "=r"((r)[5]),  "=r"((r)[6]),  "=r"((r)[7]), \
          "=r"((r)[8]),  "=r"((r)[9]),  "=r"((r)[10]), "=r"((r)[11]), \
          "=r"((r)[12]), "=r"((r)[13]), "=r"((r)[14]), "=r"((r)[15]), \
          "=r"((r)[16]), "=r"((r)[17]), "=r"((r)[18]), "=r"((r)[19]), \
          "=r"((r)[20]), "=r"((r)[21]), "=r"((r)[22]), "=r"((r)[23]), \
          "=r"((r)[24]), "=r"((r)[25]), "=r"((r)[26]), "=r"((r)[27]), \
          "=r"((r)[28]), "=r"((r)[29]), "=r"((r)[30]), "=r"((r)[31]) \
        : "r"(tmem_addr))

// SMEM descriptor: SW128, Blackwell (version=1), SBO=64, LBO=1
static __device__ __forceinline__ uint64_t make_desc(uint32_t addr) {
    const uint64_t base = (uint64_t(2) << 61) | (uint64_t(1) << 46) |
                          (uint64_t(64) << 32) | (uint64_t(1) << 16);
    return base | ((uint64_t)(addr >> 4) & 0x3FFF);
}

// tcgen05.mma kind::tf32, SS, cta_group::1
__device__ __forceinline__ void mma_tf32_ss(uint32_t d, uint64_t ad, uint64_t bd,
                                            uint32_t idesc, bool acc) {
    uint32_t en = acc ? 1u : 0u;
    asm volatile(
        "{\n\t.reg .pred p;\n\t"
        "setp.ne.u32 p, %5, 0;\n\t"
        "tcgen05.mma.cta_group::1.kind::tf32 [%0], %1, %2, %3, {%4, %4, %4, %4}, p;\n\t}"
        :: "r"(d), "l"(ad), "l"(bd), "r"(idesc), "r"(0u), "r"(en) : "memory");
}

// idesc: c=F32(1@[4]), a=TF32(2@[7]), b=TF32(2@[10]), N=64 (8@[17]), M=128 (8@[24])
#define IDESC_TF32 ((1u << 4) | (2u << 7) | (2u << 10) | (8u << 17) | (8u << 24))
#endif  // HAS_TCGEN05

// ---------------- SMEM layout (edge kernel, dynamic) ----------------
// Double-buffered U: bank b at b*32768 (32 KB each)
#define OFF_WHI  65536       // 64x64 f32 swizzled (16384)
#define OFF_HJ   98304       // 16x64 f32 (4096)
#define OFF_WJ   102400      // 64 f32
#define OFF_B2   102656      // 64 f32
#define OFF_TPTR 102912
#define OFF_MBAR 102928      // 6 mbarriers: ufull[2], mdone[2], edone[2]
#define SMEM_EDGE 102976
// fallback-only offsets (reuse U buffer space)
#define OFF_FHI  32768
#define OFF_FJ   33792

// ============================================================
// Init: h0 = 0; hi/hj terms for h=0
// ============================================================
__global__ void init_kernel(const float* __restrict__ b, const float* __restrict__ W1,
                            const float* __restrict__ b1) {
    int idx = blockIdx.x * 256 + threadIdx.x;
    int node = idx >> 6, c = idx & 63;
    g_hi[idx] = b[node] * W1[c * 35 + 33];
    g_hj[idx] = fmaf(b[node], W1[c * 35 + 34], b1[c]);
    if (c < 16) g_h[node * 16 + c] = 0.0f;
}

// ============================================================
// Edge kernel: warp-specialized tcgen05 tf32 (1-pass, W rna)
//   warps 0-3: U producers (2 i-rows each), packed f32x2 math
//   warps 4-7: per-subpartition consumers; warp 4 issues MMAs.
// grid (32 j-tiles, 8 i-chunks), block 256, 2 CTAs/SM, PDL
// ============================================================
__global__ __launch_bounds__(256, 2) void edge_tc_kernel(const float* __restrict__ J,
                                                         const float* __restrict__ W1,
                                                         const float* __restrict__ W2,
                                                         const float* __restrict__ b2) {
    extern __shared__ __align__(1024) char smem[];
    const int t = threadIdx.x;
    const int jt = blockIdx.x, ic = blockIdx.y;
    const int j0 = jt * 16;

    float* sHj = (float*)(smem + OFF_HJ);
    float* swJ = (float*)(smem + OFF_WJ);
    float* sB2 = (float*)(smem + OFF_B2);

#if HAS_TCGEN05
    const uint32_t sbase = smem_u32(smem);
    const int wid = t >> 5, lid = t & 31;

    if (wid == 0) {
        TCGEN05_ALLOC(sbase + OFF_TPTR, 128);
        TCGEN05_RELINQ();
    }
    if (t == 0) {
        MBARRIER_INIT(sbase + OFF_MBAR + 0, 4);   // ufull[0]
        MBARRIER_INIT(sbase + OFF_MBAR + 8, 4);   // ufull[1]
        MBARRIER_INIT(sbase + OFF_MBAR + 16, 1);  // mdone[0]
        MBARRIER_INIT(sbase + OFF_MBAR + 24, 1);  // mdone[1]
        MBARRIER_INIT(sbase + OFF_MBAR + 32, 4);  // edone[0]
        MBARRIER_INIT(sbase + OFF_MBAR + 40, 4);  // edone[1]
    }

    // stage W2 (rna-rounded tf32, single pass) — before the PDL dependency sync
#pragma unroll
    for (int q = 0; q < 16; q++) {
        int idx = t + q * 256;
        int c = idx >> 6, k = idx & 63;
        float whi = tf32_rna(W2[c * 64 + k]);
        uint32_t byte = (((c >> 3) + ((k >> 5) << 3)) << 10) + ((c & 7) << 7) + ((k & 31) << 2);
        byte = sw128(byte);
        *(float*)(smem + OFF_WHI + byte) = whi;
    }
    if (t < 64) { swJ[t] = W1[t * 35 + 32]; sB2[t] = b2[t]; }

    // wait for upstream kernel (mj_gru / init) results before touching g_hj / g_hi
    cudaGridDependencySynchronize();

#pragma unroll
    for (int q = 0; q < 4; q++) {
        int idx = t + q * 256;
        sHj[idx] = g_hj[(j0 + (idx >> 6)) * 64 + (idx & 63)];
    }
    FENCE_PROXY_ASYNC();
    __syncthreads();

    const uint32_t tmem = *(volatile uint32_t*)(smem + OFF_TPTR);
    const uint32_t mb_ufull = sbase + OFF_MBAR;
    const uint32_t mb_mdone = sbase + OFF_MBAR + 16;
    const uint32_t mb_edone = sbase + OFF_MBAR + 32;

    if (wid < 4) {
        // ================= producer warps (packed f32x2) =================
        const int k0 = (lid & 15) * 4;
        const unsigned long long wq2a = pk2(swJ[k0], swJ[k0 + 1]);
        const unsigned long long wq2b = pk2(swJ[k0 + 2], swJ[k0 + 3]);
        const uint32_t kpart = ((uint32_t)(k0 >> 5) << 14) + ((k0 & 31) << 2);
        const int ii = lid >> 4;
        const int ebase = (2 * wid + ii) * 16;
        const int ibase = ic * 64;

        float4 hv = *(const float4*)&g_hi[(ibase + 2 * wid + ii) * 64 + k0];
        float jp = J[(ibase + 2 * wid + ii) * NN + j0 + (lid & 15)];

        for (int r = 0; r < 8; r++) {
            const int b = r & 1;
            if (r >= 2) MBARRIER_WAIT_PARITY(mb_mdone + b * 8, ((r - 2) >> 1) & 1);
            char* ubase = smem + b * 32768;
            const unsigned long long hv2a = pk2(hv.x, hv.y);
            const unsigned long long hv2b = pk2(hv.z, hv.w);
#pragma unroll
            for (int m = 0; m < 16; m++) {
                const float Jv = __shfl_sync(0xFFFFFFFFu, jp, (lid & 16) + m);
                const ulonglong2 hj2 = *(const ulonglong2*)&sHj[m * 64 + k0];
                const unsigned long long jv2 = pk2(Jv, Jv);
                unsigned long long t0 = fma2v(jv2, wq2a, add2(hv2a, hj2.x));
                unsigned long long t1 = fma2v(jv2, wq2b, add2(hv2b, hj2.y));
                const float2 a = upk2(t0);
                const float2 c = upk2(t1);
                const int e = ebase + m;
                float4 u;
                u.x = fmaxf(a.x, 0.0f);
                u.y = fmaxf(a.y, 0.0f);
                u.z = fmaxf(c.x, 0.0f);
                u.w = fmaxf(c.y, 0.0f);
                uint32_t byte = ((uint32_t)(e >> 3) << 10) + ((e & 7) << 7) + kpart;
                byte = sw128(byte);
                *(float4*)(ubase + byte) = u;
            }
            float4 hn = make_float4(0.f, 0.f, 0.f, 0.f);
            float jn = 0.f;
            if (r < 7) {
                const int i0n = ibase + (r + 1) * 8 + 2 * wid + ii;
                hn = *(const float4*)&g_hi[i0n * 64 + k0];
                jn = J[i0n * NN + j0 + (lid & 15)];
            }
            FENCE_PROXY_ASYNC();
            __syncwarp();
            if (lid == 0) MBARRIER_ARRIVE(mb_ufull + b * 8);
            hv = hn; jp = jn;
        }
    } else {
        // ================= consumer warps (wid 4-7) =================
        const uint64_t dBhi = make_desc(sbase + OFF_WHI);
        const uint32_t offA[8] = {0, 2, 4, 6, 1024, 1026, 1028, 1030};
        const uint32_t offB[8] = {0, 2, 4, 6, 512, 514, 516, 518};

        float ysum[64];
#pragma unroll
        for (int c = 0; c < 64; c++) ysum[c] = 0.0f;

        for (int r = 0; r <= 8; r++) {
            // ---- issuer (warp 4 only) ----
            if (wid == 4 && r < 8) {
                const int b = r & 1;
                MBARRIER_WAIT_PARITY(mb_ufull + b * 8, (r >> 1) & 1);
                if (r >= 2) MBARRIER_WAIT_PARITY(mb_edone + b * 8, ((r - 2) >> 1) & 1);
                TCGEN05_FENCE_AFTER();
                if (elect_one()) {
                    const uint64_t dA = make_desc(sbase + b * 32768);
                    const uint32_t dst = tmem + b * 64;
#pragma unroll
                    for (int s = 0; s < 8; s++)
                        mma_tf32_ss(dst, dA + offA[s], dBhi + offB[s], IDESC_TF32, s > 0);
                    TCGEN05_COMMIT(mb_mdone + b * 8);
                }
            }
            // ---- epilogue for round r-1 ----
            if (r >= 1) {
                const int pr = r - 1;
                const int pb = pr & 1;
                MBARRIER_WAIT_PARITY(mb_mdone + pb * 8, (pr >> 1) & 1);
                TCGEN05_FENCE_AFTER();
                uint32_t tmp[32];
                TCGEN05_LD_32X32B_X32(tmp, tmem + pb * 64);
                TCGEN05_WAIT_LD();
#pragma unroll
                for (int c4 = 0; c4 < 8; c4++) {
                    const float4 b4 = *(const float4*)&sB2[c4 * 4];
                    ysum[c4 * 4 + 0] += fmaxf(__uint_as_float(tmp[c4 * 4 + 0]) + b4.x, 0.0f);
                    ysum[c4 * 4 + 1] += fmaxf(__uint_as_float(tmp[c4 * 4 + 1]) + b4.y, 0.0f);
                    ysum[c4 * 4 + 2] += fmaxf(__uint_as_float(tmp[c4 * 4 + 2]) + b4.z, 0.0f);
                    ysum[c4 * 4 + 3] += fmaxf(__uint_as_float(tmp[c4 * 4 + 3]) + b4.w, 0.0f);
                }
                TCGEN05_LD_32X32B_X32(tmp, tmem + pb * 64 + 32);
                TCGEN05_WAIT_LD();
#pragma unroll
                for (int c4 = 0; c4 < 8; c4++) {
                    const float4 b4 = *(const float4*)&sB2[32 + c4 * 4];
                    ysum[32 + c4 * 4 + 0] += fmaxf(__uint_as_float(tmp[c4 * 4 + 0]) + b4.x, 0.0f);
                    ysum[32 + c4 * 4 + 1] += fmaxf(__uint_as_float(tmp[c4 * 4 + 1]) + b4.y, 0.0f);
                    ysum[32 + c4 * 4 + 2] += fmaxf(__uint_as_float(tmp[c4 * 4 + 2]) + b4.z, 0.0f);
                    ysum[32 + c4 * 4 + 3] += fmaxf(__uint_as_float(tmp[c4 * 4 + 3]) + b4.w, 0.0f);
                }
                TCGEN05_FENCE_BEFORE();
                __syncwarp();
                if (lid == 0) MBARRIER_ARRIVE(mb_edone + pb * 8);
            }
        }

        // ---- cross-lane reduce over i-slots, write sRed ----
        const int sp = wid & 3;
        float* sRed = (float*)smem;   // [4 sp][16 jj][64 ch]
#pragma unroll
        for (int c4 = 0; c4 < 16; c4++) {
            float4 v;
            v.x = ysum[c4 * 4 + 0] + __shfl_xor_sync(0xFFFFFFFFu, ysum[c4 * 4 + 0], 16);
            v.y = ysum[c4 * 4 + 1] + __shfl_xor_sync(0xFFFFFFFFu, ysum[c4 * 4 + 1], 16);
            v.z = ysum[c4 * 4 + 2] + __shfl_xor_sync(0xFFFFFFFFu, ysum[c4 * 4 + 2], 16);
            v.w = ysum[c4 * 4 + 3] + __shfl_xor_sync(0xFFFFFFFFu, ysum[c4 * 4 + 3], 16);
            if (lid < 16) *(float4*)&sRed[(sp * 16 + lid) * 64 + c4 * 4] = v;
        }
    }

    __syncthreads();

    // final sum over 4 subpartitions, write partials (all 256 threads)
    {
        float* sRed = (float*)smem;
#pragma unroll
        for (int q = 0; q < 4; q++) {
            int o = t * 4 + q;
            int jj = o >> 6, ch = o & 63;
            float s = sRed[(0 * 16 + jj) * 64 + ch] + sRed[(1 * 16 + jj) * 64 + ch] +
                      sRed[(2 * 16 + jj) * 64 + ch] + sRed[(3 * 16 + jj) * 64 + ch];
            g_ysum_part[(ic * NN + j0 + jj) * 64 + ch] = s;
        }
    }

    __syncthreads();
    // all global writes done — allow dependent kernel to launch
    cudaTriggerProgrammaticLaunchCompletion();

    if (t == 0) {
#pragma unroll
        for (int m = 0; m < 6; m++) MBARRIER_INVAL(sbase + OFF_MBAR + m * 8);
    }
    if (wid == 0) TCGEN05_DEALLOC(tmem, 128);

#else  // ---------- scalar fallback (family-PTX pass; never runs on sm_103a) ----------
    float* sW2 = (float*)(smem + OFF_WHI);     // [c][k] linear
    float* sU  = (float*)smem;                 // [k][16]
    float* sHi = (float*)(smem + OFF_FHI);
    float* sJ  = (float*)(smem + OFF_FJ);

#pragma unroll
    for (int q = 0; q < 16; q++) {
        int idx = t + q * 256;
        sW2[idx] = W2[idx];
    }
    if (t < 64) { swJ[t] = W1[t * 35 + 32]; sB2[t] = b2[t]; }
    cudaGridDependencySynchronize();
#pragma unroll
    for (int q = 0; q < 4; q++) {
        int idx = t + q * 256;
        sHj[idx] = g_hj[(j0 + (idx >> 6)) * 64 + (idx & 63)];
    }
    __syncthreads();

    const int jjf = t >> 4;
    float acc[4] = {0.f, 0.f, 0.f, 0.f};
    for (int i = ic * 64; i < ic * 64 + 64; i++) {
        if (t < 64) sHi[t] = g_hi[i * 64 + t];
        if (t < 16) sJ[t] = J[i * NN + j0 + t];
        __syncthreads();
#pragma unroll
        for (int q = 0; q < 4; q++) {
            int idx = t * 4 + q;
            int k = idx >> 4, jl = idx & 15;
            float u = fmaf(sJ[jl], swJ[k], sHi[k] + sHj[jl * 64 + k]);
            sU[k * 16 + jl] = fmaxf(u, 0.0f);
        }
        __syncthreads();
#pragma unroll
        for (int q = 0; q < 4; q++) {
            int ch = (t & 15) * 4 + q;
            float v = sB2[ch];
            for (int k = 0; k < 64; k++) v = fmaf(sW2[ch * 64 + k], sU[k * 16 + jjf], v);
            acc[q] += fmaxf(v, 0.0f);
        }
        __syncthreads();
    }
#pragma unroll
    for (int q = 0; q < 4; q++) {
        int ch = (t & 15) * 4 + q;
        g_ysum_part[(ic * NN + j0 + jjf) * 64 + ch] = acc[q];
    }
    cudaTriggerProgrammaticLaunchCompletion();
#endif
}

// ============================================================
// Fused m_j + GRU + next-step hi/hj (steps 0-3) or readout (step 4)
// grid 128, block 128 (4 nodes per block)
// ============================================================
__global__ void mj_gru_kernel(const float* __restrict__ W3, const float* __restrict__ b3,
                              const float* __restrict__ W_ih, const float* __restrict__ b_ih,
                              const float* __restrict__ W_hh, const float* __restrict__ b_hh,
                              const float* __restrict__ W1, const float* __restrict__ b1,
                              const float* __restrict__ bn,
                              const float* __restrict__ Wr1, const float* __restrict__ br1,
                              const float* __restrict__ Wr2, const float* __restrict__ br2,
                              const float* __restrict__ Wr3, const float* __restrict__ br3,
                              float* __restrict__ out, int step) {
    __shared__ float sY[4][64];
    __shared__ float sH[4][16], sMJ[4][32], sGI[4][48], sGH[4][48], sHn[4][16];
    __shared__ float sR2[4][64], sR3[4][2];
    const int t = threadIdx.x;
    const int n0 = blockIdx.x * 4;

    cudaGridDependencySynchronize();

    // reduce 8 partials: 4 nodes x 64 ch
#pragma unroll
    for (int q = 0; q < 2; q++) {
        int idx = t + q * 128;
        int jl = idx >> 6, k = idx & 63;
        float s = 0.0f;
#pragma unroll
        for (int p = 0; p < 8; p++) s += g_ysum_part[(p * NN + n0 + jl) * 64 + k];
        sY[jl][k] = s;
    }
    if (t < 64) { int nl = t >> 4, s = t & 15; sH[nl][s] = g_h[(n0 + nl) * 16 + s]; }
    __syncthreads();

    // m_j: 4 nodes x 32 ch = 128 threads
    {
        const int jl = t >> 5, c2 = t & 31;
        float s = 512.0f * b3[c2];
#pragma unroll
        for (int k = 0; k < 64; k++) s = fmaf(W3[c2 * 64 + k], sY[jl][k], s);
        sMJ[jl][c2] = s;
    }
    __syncthreads();

    // gates: 4 nodes x 48 = 192
#pragma unroll
    for (int q = 0; q < 2; q++) {
        int idx = t + q * 128;
        if (idx < 192) {
            int nl = idx / 48, g = idx % 48;
            float gi = b_ih[g], gh = b_hh[g];
#pragma unroll
            for (int s = 0; s < 16; s++) {
                gi = fmaf(sH[nl][s], W_ih[g * 48 + s], gi);
                gh = fmaf(sH[nl][s], W_hh[g * 16 + s], gh);
            }
#pragma unroll
            for (int m = 0; m < 32; m++) gi = fmaf(sMJ[nl][m], W_ih[g * 48 + 16 + m], gi);
            sGI[nl][g] = gi;
            sGH[nl][g] = gh;
        }
    }
    __syncthreads();

    if (t < 64) {
        int nl = t >> 4, s = t & 15;
        float r = sigmoidf(sGI[nl][s] + sGH[nl][s]);
        float z = sigmoidf(sGI[nl][16 + s] + sGH[nl][16 + s]);
        float nv = tanhf(sGI[nl][32 + s] + r * sGH[nl][32 + s]);
        float hn = (1.0f - z) * nv + z * sH[nl][s];
        sHn[nl][s] = hn;
        g_h[(n0 + nl) * 16 + s] = hn;
    }
    __syncthreads();

    if (step < 4) {
        // hi/hj for next step: 4 nodes x 64 c x {hi,hj} = 512 outputs
#pragma unroll
        for (int q = 0; q < 4; q++) {
            int idx = t + q * 128;
            int nl = idx >> 7, rem = idx & 127;
            int c = rem & 63, which = rem >> 6;
            int ng = n0 + nl;
            const float* w = &W1[c * 35 + (which ? 16 : 0)];
            float s = which ? fmaf(bn[ng], W1[c * 35 + 34], b1[c]) : bn[ng] * W1[c * 35 + 33];
#pragma unroll
            for (int sd = 0; sd < 16; sd++) s = fmaf(sHn[nl][sd], w[sd], s);
            if (which) g_hj[ng * 64 + c] = s;
            else       g_hi[ng * 64 + c] = s;
        }
    } else {
        // fused readout for these 4 nodes
#pragma unroll
        for (int q = 0; q < 2; q++) {
            int idx = t + q * 128;
            int nl = idx >> 6, o = idx & 63;
            float s = br1[o];
#pragma unroll
            for (int k = 0; k < 16; k++) s = fmaf(sHn[nl][k], Wr1[o * 16 + k], s);
            sY[nl][o] = fmaxf(s, 0.0f);
        }
        __syncthreads();
#pragma unroll
        for (int q = 0; q < 2; q++) {
            int idx = t + q * 128;
            int nl = idx >> 6, o = idx & 63;
            float s = br2[o];
#pragma unroll
            for (int k = 0; k < 64; k++) s = fmaf(sY[nl][k], Wr2[o * 64 + k], s);
            sR2[nl][o] = fmaxf(s, 0.0f);
        }
        __syncthreads();
        if (t < 8) {
            int nl = t >> 1, o = t & 1;
            float s = br3[o];
#pragma unroll
            for (int k = 0; k < 64; k++) s = fmaf(sR2[nl][k], Wr3[o * 64 + k], s);
            sR3[nl][o] = sigmoidf(s);
        }
        __syncthreads();
        if (t < 8) {
            int nl = t >> 1, o = t & 1;
            out[(n0 + nl) * 2 + o] = sR3[nl][o] / (sR3[nl][0] + sR3[nl][1]);
        }
    }
}

// ============================================================
// host-side PDL launch helper
// ============================================================
static inline void launch_pdl(const void* func, dim3 grid, dim3 block, size_t smem,
                              void** args) {
    cudaLaunchConfig_t cfg = {};
    cfg.gridDim = grid;
    cfg.blockDim = block;
    cfg.dynamicSmemBytes = smem;
    cfg.stream = 0;
    cudaLaunchAttribute attr[1];
    attr[0].id = cudaLaunchAttributeProgrammaticStreamSerialization;
    attr[0].val.programmaticStreamSerializationAllowed = 1;
    cfg.attrs = attr;
    cfg.numAttrs = 1;
    cudaLaunchKernelExC(&cfg, func, args);
}

// ============================================================
extern "C" void kernel_launch(void* const* d_in, const int* in_sizes, int n_in,
                              void* d_out, int out_size) {
    const float* J    = (const float*)d_in[0];
    const float* b    = (const float*)d_in[1];
    const float* W1   = (const float*)d_in[2];
    const float* b1   = (const float*)d_in[3];
    const float* W2   = (const float*)d_in[4];
    const float* b2   = (const float*)d_in[5];
    const float* W3   = (const float*)d_in[6];
    const float* b3   = (const float*)d_in[7];
    const float* W_ih = (const float*)d_in[8];
    const float* b_ih = (const float*)d_in[9];
    const float* W_hh = (const float*)d_in[10];
    const float* b_hh = (const float*)d_in[11];
    const float* Wr1  = (const float*)d_in[12];
    const float* br1  = (const float*)d_in[13];
    const float* Wr2  = (const float*)d_in[14];
    const float* br2  = (const float*)d_in[15];
    const float* Wr3  = (const float*)d_in[16];
    const float* br3  = (const float*)d_in[17];
    float* out = (float*)d_out;

    cudaFuncSetAttribute(edge_tc_kernel, cudaFuncAttributeMaxDynamicSharedMemorySize, SMEM_EDGE);

    init_kernel<<<128, 256>>>(b, W1, b1);
    for (int step = 0; step < 5; step++) {
        {
            void* args[] = {(void*)&J, (void*)&W1, (void*)&W2, (void*)&b2};
            launch_pdl((const void*)edge_tc_kernel, dim3(32, 8), dim3(256), SMEM_EDGE, args);
        }
        {
            void* args[] = {(void*)&W3, (void*)&b3, (void*)&W_ih, (void*)&b_ih,
                            (void*)&W_hh, (void*)&b_hh, (void*)&W1, (void*)&b1,
                            (void*)&b, (void*)&Wr1, (void*)&br1, (void*)&Wr2,
                            (void*)&br2, (void*)&Wr3, (void*)&br3, (void*)&out,
                            (void*)&step};
            launch_pdl((const void*)mj_gru_kernel, dim3(128), dim3(128), 0, args);
        }
    }
}

// round 14
// speedup vs baseline: 1.7004x; 1.3017x over previous
#include <cuda_runtime.h>
#include <cstdint>
#include <math.h>

#define NN 512

#if defined(__CUDA_ARCH_FEAT_SM103_ALL) || defined(__CUDA_ARCH_FEAT_SM100_ALL)
#define HAS_TCGEN05 1
#else
#define HAS_TCGEN05 0
#endif

// ---------------- device scratch ----------------
__device__ float g_h[NN * 16];
__device__ float g_hi[NN * 64];
__device__ float g_hj[NN * 64];
__device__ float g_ysum_part[8 * NN * 64];

// ---------------- PTX helpers ----------------
__device__ __forceinline__ uint32_t smem_u32(const void* p) {
    uint32_t a;
    asm("{ .reg .u64 t; cvta.to.shared.u64 t, %1; cvt.u32.u64 %0, t; }" : "=r"(a) : "l"(p));
    return a;
}
__device__ __forceinline__ float tf32_rna(float x) {
    float r;
    asm("cvt.rna.tf32.f32 %0, %1;" : "=f"(r) : "f"(x));
    return r;
}
__device__ __forceinline__ uint32_t sw128(uint32_t b) { return b ^ ((b >> 3) & 0x70); }
__device__ __forceinline__ float sigmoidf(float x) { return 1.0f / (1.0f + expf(-x)); }

#if HAS_TCGEN05
// ---- packed f32x2 ----
__device__ __forceinline__ unsigned long long pk2(float lo, float hi) {
    unsigned long long r;
    asm("mov.b64 %0, {%1, %2};" : "=l"(r) : "f"(lo), "f"(hi));
    return r;
}
__device__ __forceinline__ unsigned long long add2(unsigned long long a, unsigned long long b) {
    unsigned long long r;
    asm("add.rn.f32x2 %0, %1, %2;" : "=l"(r) : "l"(a), "l"(b));
    return r;
}
__device__ __forceinline__ unsigned long long fma2v(unsigned long long a, unsigned long long b,
                                                   unsigned long long c) {
    unsigned long long r;
    asm("fma.rn.f32x2 %0, %1, %2, %3;" : "=l"(r) : "l"(a), "l"(b), "l"(c));
    return r;
}
__device__ __forceinline__ float2 upk2(unsigned long long v) {
    float2 f;
    asm("mov.b64 {%0, %1}, %2;" : "=f"(f.x), "=f"(f.y) : "l"(v));
    return f;
}

__device__ __forceinline__ uint32_t elect_one() {
    uint32_t p;
    asm volatile("{ .reg .pred p; elect.sync _|p, 0xFFFFFFFF; selp.b32 %0, 1, 0, p; }" : "=r"(p));
    return p;
}
#define MBARRIER_INIT(addr, cnt) \
    asm volatile("mbarrier.init.shared.b64 [%0], %1;" :: "r"((uint32_t)(addr)), "r"((uint32_t)(cnt)) : "memory")
#define MBARRIER_INVAL(addr) \
    asm volatile("mbarrier.inval.shared.b64 [%0];" :: "r"((uint32_t)(addr)) : "memory")
#define MBARRIER_ARRIVE(addr) \
    asm volatile("mbarrier.arrive.shared.b64 _, [%0];" :: "r"((uint32_t)(addr)) : "memory")
#define MBARRIER_WAIT_PARITY(mbar_smem_addr, phase_parity) do { \
    uint32_t _mbar = (uint32_t)(mbar_smem_addr); \
    uint32_t _parity = (uint32_t)(phase_parity); \
    uint32_t _done; \
    asm volatile( \
        "{\n\t.reg .pred p;\n\t" \
        "mbarrier.try_wait.parity.acquire.cta.shared::cta.b64 p, [%1], %2;\n\t" \
        "selp.b32 %0, 1, 0, p;\n\t}" \
        : "=r"(_done) : "r"(_mbar), "r"(_parity) : "memory"); \
    if (!_done) { \
        asm volatile( \
            "{\n\t.reg .pred P1;\n\t" \
            "WAIT_LOOP_%=:\n\t" \
            "mbarrier.try_wait.parity.acquire.cta.shared::cta.b64 P1, [%0], %1, 0x989680;\n\t" \
            "@P1 bra.uni WAIT_DONE_%=;\n\t" \
            "bra.uni WAIT_LOOP_%=;\n\t" \
            "WAIT_DONE_%=:\n\t}" \
            :: "r"(_mbar), "r"(_parity) : "memory"); \
    } \
} while(0)
#define TCGEN05_ALLOC(saddr, ncols) \
    asm volatile("tcgen05.alloc.cta_group::1.sync.aligned.shared::cta.b32 [%0], %1;" \
                 :: "r"((uint32_t)(saddr)), "r"((uint32_t)(ncols)) : "memory")
#define TCGEN05_DEALLOC(taddr, ncols) \
    asm volatile("tcgen05.dealloc.cta_group::1.sync.aligned.b32 %0, %1;" :: "r"(taddr), "r"((uint32_t)(ncols)))
#define TCGEN05_RELINQ() \
    asm volatile("tcgen05.relinquish_alloc_permit.cta_group::1.sync.aligned;")
#define TCGEN05_COMMIT(mbar) \
    asm volatile("tcgen05.commit.cta_group::1.mbarrier::arrive::one.shared::cluster.b64 [%0];" \
                 :: "r"((uint32_t)(mbar)) : "memory")
#define TCGEN05_FENCE_AFTER()  asm volatile("tcgen05.fence::after_thread_sync;" ::: "memory")
#define TCGEN05_FENCE_BEFORE() asm volatile("tcgen05.fence::before_thread_sync;" ::: "memory")
#define TCGEN05_WAIT_LD()      asm volatile("tcgen05.wait::ld.sync.aligned;" ::: "memory")
#define FENCE_PROXY_ASYNC()    asm volatile("fence.proxy.async.shared::cta;" ::: "memory")

#define TCGEN05_LD_32X32B_X32(r, tmem_addr) \
    asm volatile( \
        "tcgen05.ld.sync.aligned.32x32b.x32.b32 " \
        "{%0, %1, %2, %3, %4, %5, %6, %7, " \
        " %8, %9, %10, %11, %12, %13, %14, %15, " \
        " %16, %17, %18, %19, %20, %21, %22, %23, " \
        " %24, %25, %26, %27, %28, %29, %30, %31}, [%32];" \
        : "=r"((r)[0]),  "=r"((r)[1]),  "=r"((r)[2]),  "=r"((r)[3]), \
          "=r"((r)[4]),  "=r"((r)[5]),  "=r"((r)[6]),  "=r"((r)[7]), \
          "=r"((r)[8]),  "=r"((r)[9]),  "=r"((r)[10]), "=r"((r)[11]), \
          "=r"((r)[12]), "=r"((r)[13]), "=r"((r)[14]), "=r"((r)[15]), \
          "=r"((r)[16]), "=r"((r)[17]), "=r"((r)[18]), "=r"((r)[19]), \
          "=r"((r)[20]), "=r"((r)[21]), "=r"((r)[22]), "=r"((r)[23]), \
          "=r"((r)[24]), "=r"((r)[25]), "=r"((r)[26]), "=r"((r)[27]), \
          "=r"((r)[28]), "=r"((r)[29]), "=r"((r)[30]), "=r"((r)[31]) \
        : "r"(tmem_addr))

// SMEM descriptor: SW128, Blackwell (version=1), SBO=64, LBO=1
static __device__ __forceinline__ uint64_t make_desc(uint32_t addr) {
    const uint64_t base = (uint64_t(2) << 61) | (uint64_t(1) << 46) |
                          (uint64_t(64) << 32) | (uint64_t(1) << 16);
    return base | ((uint64_t)(addr >> 4) & 0x3FFF);
}

// tcgen05.mma kind::tf32, SS, cta_group::1
__device__ __forceinline__ void mma_tf32_ss(uint32_t d, uint64_t ad, uint64_t bd,
                                            uint32_t idesc, bool acc) {
    uint32_t en = acc ? 1u : 0u;
    asm volatile(
        "{\n\t.reg .pred p;\n\t"
        "setp.ne.u32 p, %5, 0;\n\t"
        "tcgen05.mma.cta_group::1.kind::tf32 [%0], %1, %2, %3, {%4, %4, %4, %4}, p;\n\t}"
        :: "r"(d), "l"(ad), "l"(bd), "r"(idesc), "r"(0u), "r"(en) : "memory");
}

// idesc: c=F32(1@[4]), a=TF32(2@[7]), b=TF32(2@[10]), N=64 (8@[17]), M=128 (8@[24])
#define IDESC_TF32 ((1u << 4) | (2u << 7) | (2u << 10) | (8u << 17) | (8u << 24))
#endif  // HAS_TCGEN05

// ---------------- SMEM layout (edge kernel, dynamic) ----------------
// Double-buffered U: bank b at b*32768 (32 KB each)
#define OFF_WHI  65536       // 64x64 f32 swizzled (16384)
#define OFF_HJ   98304       // 16x64 f32 (4096)
#define OFF_WJ   102400      // 64 f32
#define OFF_B2   102656      // 64 f32
#define OFF_TPTR 102912
#define OFF_MBAR 102928      // 6 mbarriers: ufull[2], mdone[2], edone[2]
#define SMEM_EDGE 102976
// fallback-only offsets (reuse U buffer space)
#define OFF_FHI  32768
#define OFF_FJ   33792

// ============================================================
// Init: h0 = 0; hi/hj terms for h=0
// ============================================================
__global__ void init_kernel(const float* __restrict__ b, const float* __restrict__ W1,
                            const float* __restrict__ b1) {
    int idx = blockIdx.x * 256 + threadIdx.x;
    int node = idx >> 6, c = idx & 63;
    g_hi[idx] = b[node] * W1[c * 35 + 33];
    g_hj[idx] = fmaf(b[node], W1[c * 35 + 34], b1[c]);
    if (c < 16) g_h[node * 16 + c] = 0.0f;
}

// ============================================================
// Edge kernel: warp-specialized tcgen05 tf32 (1-pass, W rna)
//   warps 0-3: U producers (2 i-rows each), packed f32x2 math
//   warps 4-7: per-subpartition consumers; warp 4 issues MMAs.
// grid (32 j-tiles, 8 i-chunks), block 256, 2 CTAs/SM, PDL
// ============================================================
__global__ __launch_bounds__(256, 2) void edge_tc_kernel(const float* __restrict__ J,
                                                         const float* __restrict__ W1,
                                                         const float* __restrict__ W2,
                                                         const float* __restrict__ b2) {
    extern __shared__ __align__(1024) char smem[];
    const int t = threadIdx.x;
    const int jt = blockIdx.x, ic = blockIdx.y;
    const int j0 = jt * 16;

    float* sHj = (float*)(smem + OFF_HJ);
    float* swJ = (float*)(smem + OFF_WJ);
    float* sB2 = (float*)(smem + OFF_B2);

#if HAS_TCGEN05
    const uint32_t sbase = smem_u32(smem);
    const int wid = t >> 5, lid = t & 31;

    if (wid == 0) {
        TCGEN05_ALLOC(sbase + OFF_TPTR, 128);
        TCGEN05_RELINQ();
    }
    if (t == 0) {
        MBARRIER_INIT(sbase + OFF_MBAR + 0, 4);   // ufull[0]
        MBARRIER_INIT(sbase + OFF_MBAR + 8, 4);   // ufull[1]
        MBARRIER_INIT(sbase + OFF_MBAR + 16, 1);  // mdone[0]
        MBARRIER_INIT(sbase + OFF_MBAR + 24, 1);  // mdone[1]
        MBARRIER_INIT(sbase + OFF_MBAR + 32, 4);  // edone[0]
        MBARRIER_INIT(sbase + OFF_MBAR + 40, 4);  // edone[1]
    }

    // stage W2 (rna-rounded tf32, single pass) — before the PDL dependency sync
#pragma unroll
    for (int q = 0; q < 16; q++) {
        int idx = t + q * 256;
        int c = idx >> 6, k = idx & 63;
        float whi = tf32_rna(W2[c * 64 + k]);
        uint32_t byte = (((c >> 3) + ((k >> 5) << 3)) << 10) + ((c & 7) << 7) + ((k & 31) << 2);
        byte = sw128(byte);
        *(float*)(smem + OFF_WHI + byte) = whi;
    }
    if (t < 64) { swJ[t] = W1[t * 35 + 32]; sB2[t] = b2[t]; }

    // wait for upstream kernel (mj_gru / init) results before touching g_hj / g_hi
    cudaGridDependencySynchronize();

#pragma unroll
    for (int q = 0; q < 4; q++) {
        int idx = t + q * 256;
        sHj[idx] = g_hj[(j0 + (idx >> 6)) * 64 + (idx & 63)];
    }
    FENCE_PROXY_ASYNC();
    __syncthreads();

    const uint32_t tmem = *(volatile uint32_t*)(smem + OFF_TPTR);
    const uint32_t mb_ufull = sbase + OFF_MBAR;
    const uint32_t mb_mdone = sbase + OFF_MBAR + 16;
    const uint32_t mb_edone = sbase + OFF_MBAR + 32;

    if (wid < 4) {
        // ================= producer warps (packed f32x2) =================
        const int k0 = (lid & 15) * 4;
        const unsigned long long wq2a = pk2(swJ[k0], swJ[k0 + 1]);
        const unsigned long long wq2b = pk2(swJ[k0 + 2], swJ[k0 + 3]);
        const uint32_t kpart = ((uint32_t)(k0 >> 5) << 14) + ((k0 & 31) << 2);
        const int ii = lid >> 4;
        const int ebase = (2 * wid + ii) * 16;
        const int ibase = ic * 64;

        float4 hv = *(const float4*)&g_hi[(ibase + 2 * wid + ii) * 64 + k0];
        float jp = J[(ibase + 2 * wid + ii) * NN + j0 + (lid & 15)];

        for (int r = 0; r < 8; r++) {
            const int b = r & 1;
            if (r >= 2) MBARRIER_WAIT_PARITY(mb_mdone + b * 8, ((r - 2) >> 1) & 1);
            char* ubase = smem + b * 32768;
            const unsigned long long hv2a = pk2(hv.x, hv.y);
            const unsigned long long hv2b = pk2(hv.z, hv.w);
#pragma unroll
            for (int m = 0; m < 16; m++) {
                const float Jv = __shfl_sync(0xFFFFFFFFu, jp, (lid & 16) + m);
                const ulonglong2 hj2 = *(const ulonglong2*)&sHj[m * 64 + k0];
                const unsigned long long jv2 = pk2(Jv, Jv);
                unsigned long long t0 = fma2v(jv2, wq2a, add2(hv2a, hj2.x));
                unsigned long long t1 = fma2v(jv2, wq2b, add2(hv2b, hj2.y));
                const float2 a = upk2(t0);
                const float2 c = upk2(t1);
                const int e = ebase + m;
                float4 u;
                u.x = fmaxf(a.x, 0.0f);
                u.y = fmaxf(a.y, 0.0f);
                u.z = fmaxf(c.x, 0.0f);
                u.w = fmaxf(c.y, 0.0f);
                uint32_t byte = ((uint32_t)(e >> 3) << 10) + ((e & 7) << 7) + kpart;
                byte = sw128(byte);
                *(float4*)(ubase + byte) = u;
            }
            float4 hn = make_float4(0.f, 0.f, 0.f, 0.f);
            float jn = 0.f;
            if (r < 7) {
                const int i0n = ibase + (r + 1) * 8 + 2 * wid + ii;
                hn = *(const float4*)&g_hi[i0n * 64 + k0];
                jn = J[i0n * NN + j0 + (lid & 15)];
            }
            FENCE_PROXY_ASYNC();
            __syncwarp();
            if (lid == 0) MBARRIER_ARRIVE(mb_ufull + b * 8);
            hv = hn; jp = jn;
        }
    } else {
        // ================= consumer warps (wid 4-7) =================
        const uint64_t dBhi = make_desc(sbase + OFF_WHI);
        const uint32_t offA[8] = {0, 2, 4, 6, 1024, 1026, 1028, 1030};
        const uint32_t offB[8] = {0, 2, 4, 6, 512, 514, 516, 518};

        float ysum[64];
#pragma unroll
        for (int c = 0; c < 64; c++) ysum[c] = 0.0f;

        for (int r = 0; r <= 8; r++) {
            // ---- issuer (warp 4 only) ----
            if (wid == 4 && r < 8) {
                const int b = r & 1;
                MBARRIER_WAIT_PARITY(mb_ufull + b * 8, (r >> 1) & 1);
                if (r >= 2) MBARRIER_WAIT_PARITY(mb_edone + b * 8, ((r - 2) >> 1) & 1);
                TCGEN05_FENCE_AFTER();
                if (elect_one()) {
                    const uint64_t dA = make_desc(sbase + b * 32768);
                    const uint32_t dst = tmem + b * 64;
#pragma unroll
                    for (int s = 0; s < 8; s++)
                        mma_tf32_ss(dst, dA + offA[s], dBhi + offB[s], IDESC_TF32, s > 0);
                    TCGEN05_COMMIT(mb_mdone + b * 8);
                }
            }
            // ---- epilogue for round r-1 ----
            if (r >= 1) {
                const int pr = r - 1;
                const int pb = pr & 1;
                MBARRIER_WAIT_PARITY(mb_mdone + pb * 8, (pr >> 1) & 1);
                TCGEN05_FENCE_AFTER();
                uint32_t tmp[32];
                TCGEN05_LD_32X32B_X32(tmp, tmem + pb * 64);
                TCGEN05_WAIT_LD();
#pragma unroll
                for (int c4 = 0; c4 < 8; c4++) {
                    const float4 b4 = *(const float4*)&sB2[c4 * 4];
                    ysum[c4 * 4 + 0] += fmaxf(__uint_as_float(tmp[c4 * 4 + 0]) + b4.x, 0.0f);
                    ysum[c4 * 4 + 1] += fmaxf(__uint_as_float(tmp[c4 * 4 + 1]) + b4.y, 0.0f);
                    ysum[c4 * 4 + 2] += fmaxf(__uint_as_float(tmp[c4 * 4 + 2]) + b4.z, 0.0f);
                    ysum[c4 * 4 + 3] += fmaxf(__uint_as_float(tmp[c4 * 4 + 3]) + b4.w, 0.0f);
                }
                TCGEN05_LD_32X32B_X32(tmp, tmem + pb * 64 + 32);
                TCGEN05_WAIT_LD();
#pragma unroll
                for (int c4 = 0; c4 < 8; c4++) {
                    const float4 b4 = *(const float4*)&sB2[32 + c4 * 4];
                    ysum[32 + c4 * 4 + 0] += fmaxf(__uint_as_float(tmp[c4 * 4 + 0]) + b4.x, 0.0f);
                    ysum[32 + c4 * 4 + 1] += fmaxf(__uint_as_float(tmp[c4 * 4 + 1]) + b4.y, 0.0f);
                    ysum[32 + c4 * 4 + 2] += fmaxf(__uint_as_float(tmp[c4 * 4 + 2]) + b4.z, 0.0f);
                    ysum[32 + c4 * 4 + 3] += fmaxf(__uint_as_float(tmp[c4 * 4 + 3]) + b4.w, 0.0f);
                }
                TCGEN05_FENCE_BEFORE();
                __syncwarp();
                if (lid == 0) MBARRIER_ARRIVE(mb_edone + pb * 8);
            }
        }

        // ---- cross-lane reduce over i-slots, write sRed ----
        const int sp = wid & 3;
        float* sRed = (float*)smem;   // [4 sp][16 jj][64 ch]
#pragma unroll
        for (int c4 = 0; c4 < 16; c4++) {
            float4 v;
            v.x = ysum[c4 * 4 + 0] + __shfl_xor_sync(0xFFFFFFFFu, ysum[c4 * 4 + 0], 16);
            v.y = ysum[c4 * 4 + 1] + __shfl_xor_sync(0xFFFFFFFFu, ysum[c4 * 4 + 1], 16);
            v.z = ysum[c4 * 4 + 2] + __shfl_xor_sync(0xFFFFFFFFu, ysum[c4 * 4 + 2], 16);
            v.w = ysum[c4 * 4 + 3] + __shfl_xor_sync(0xFFFFFFFFu, ysum[c4 * 4 + 3], 16);
            if (lid < 16) *(float4*)&sRed[(sp * 16 + lid) * 64 + c4 * 4] = v;
        }
    }

    __syncthreads();

    // final sum over 4 subpartitions, write partials (all 256 threads)
    {
        float* sRed = (float*)smem;
#pragma unroll
        for (int q = 0; q < 4; q++) {
            int o = t * 4 + q;
            int jj = o >> 6, ch = o & 63;
            float s = sRed[(0 * 16 + jj) * 64 + ch] + sRed[(1 * 16 + jj) * 64 + ch] +
                      sRed[(2 * 16 + jj) * 64 + ch] + sRed[(3 * 16 + jj) * 64 + ch];
            g_ysum_part[(ic * NN + j0 + jj) * 64 + ch] = s;
        }
    }

    __syncthreads();
    // all global writes done — allow dependent kernel to launch
    cudaTriggerProgrammaticLaunchCompletion();

    if (t == 0) {
#pragma unroll
        for (int m = 0; m < 6; m++) MBARRIER_INVAL(sbase + OFF_MBAR + m * 8);
    }
    if (wid == 0) TCGEN05_DEALLOC(tmem, 128);

#else  // ---------- scalar fallback (family-PTX pass; never runs on sm_103a) ----------
    float* sW2 = (float*)(smem + OFF_WHI);     // [c][k] linear
    float* sU  = (float*)smem;                 // [k][16]
    float* sHi = (float*)(smem + OFF_FHI);
    float* sJ  = (float*)(smem + OFF_FJ);

#pragma unroll
    for (int q = 0; q < 16; q++) {
        int idx = t + q * 256;
        sW2[idx] = W2[idx];
    }
    if (t < 64) { swJ[t] = W1[t * 35 + 32]; sB2[t] = b2[t]; }
    cudaGridDependencySynchronize();
#pragma unroll
    for (int q = 0; q < 4; q++) {
        int idx = t + q * 256;
        sHj[idx] = g_hj[(j0 + (idx >> 6)) * 64 + (idx & 63)];
    }
    __syncthreads();

    const int jjf = t >> 4;
    float acc[4] = {0.f, 0.f, 0.f, 0.f};
    for (int i = ic * 64; i < ic * 64 + 64; i++) {
        if (t < 64) sHi[t] = g_hi[i * 64 + t];
        if (t < 16) sJ[t] = J[i * NN + j0 + t];
        __syncthreads();
#pragma unroll
        for (int q = 0; q < 4; q++) {
            int idx = t * 4 + q;
            int k = idx >> 4, jl = idx & 15;
            float u = fmaf(sJ[jl], swJ[k], sHi[k] + sHj[jl * 64 + k]);
            sU[k * 16 + jl] = fmaxf(u, 0.0f);
        }
        __syncthreads();
#pragma unroll
        for (int q = 0; q < 4; q++) {
            int ch = (t & 15) * 4 + q;
            float v = sB2[ch];
            for (int k = 0; k < 64; k++) v = fmaf(sW2[ch * 64 + k], sU[k * 16 + jjf], v);
            acc[q] += fmaxf(v, 0.0f);
        }
        __syncthreads();
    }
#pragma unroll
    for (int q = 0; q < 4; q++) {
        int ch = (t & 15) * 4 + q;
        g_ysum_part[(ic * NN + j0 + jjf) * 64 + ch] = acc[q];
    }
    cudaTriggerProgrammaticLaunchCompletion();
#endif
}

// ============================================================
// Fused m_j + GRU + next-step hi/hj (steps 0-3) or readout (step 4)
// grid 128, block 128 (4 nodes per block)
// Weights prestaged into smem BEFORE the PDL dependency sync.
// ============================================================
__global__ void mj_gru_kernel(const float* __restrict__ W3, const float* __restrict__ b3,
                              const float* __restrict__ W_ih, const float* __restrict__ b_ih,
                              const float* __restrict__ W_hh, const float* __restrict__ b_hh,
                              const float* __restrict__ W1, const float* __restrict__ b1,
                              const float* __restrict__ bn,
                              const float* __restrict__ Wr1, const float* __restrict__ br1,
                              const float* __restrict__ Wr2, const float* __restrict__ br2,
                              const float* __restrict__ Wr3, const float* __restrict__ br3,
                              float* __restrict__ out, int step) {
    __shared__ float sY[4][64];
    __shared__ float sH[4][16], sMJ[4][32], sGI[4][48], sGH[4][48], sHn[4][16];
    __shared__ float sR2[4][64], sR3[4][2];
    __shared__ float sW3[2048];     // [32][64]
    __shared__ float sWih[2304];    // [48][48]
    __shared__ float sWhh[768];     // [48][16]
    __shared__ float sW1[2240];     // [64][35]
    const int t = threadIdx.x;
    const int n0 = blockIdx.x * 4;

    // ---- prestage weights (inputs only; overlaps upstream edge kernel via PDL) ----
#pragma unroll
    for (int q = 0; q < 16; q++) sW3[t + q * 128] = W3[t + q * 128];
#pragma unroll
    for (int q = 0; q < 18; q++) sWih[t + q * 128] = W_ih[t + q * 128];
#pragma unroll
    for (int q = 0; q < 6; q++) sWhh[t + q * 128] = W_hh[t + q * 128];
#pragma unroll
    for (int q = 0; q < 18; q++) {
        int idx = t + q * 128;
        if (idx < 2240) sW1[idx] = W1[idx];
    }

    cudaGridDependencySynchronize();

    // reduce 8 partials: 4 nodes x 64 ch
#pragma unroll
    for (int q = 0; q < 2; q++) {
        int idx = t + q * 128;
        int jl = idx >> 6, k = idx & 63;
        float s = 0.0f;
#pragma unroll
        for (int p = 0; p < 8; p++) s += g_ysum_part[(p * NN + n0 + jl) * 64 + k];
        sY[jl][k] = s;
    }
    if (t < 64) { int nl = t >> 4, s = t & 15; sH[nl][s] = g_h[(n0 + nl) * 16 + s]; }
    __syncthreads();

    // m_j: 4 nodes x 32 ch = 128 threads
    {
        const int jl = t >> 5, c2 = t & 31;
        float s = 512.0f * b3[c2];
#pragma unroll
        for (int k = 0; k < 64; k++) s = fmaf(sW3[c2 * 64 + k], sY[jl][k], s);
        sMJ[jl][c2] = s;
    }
    __syncthreads();

    // gates: 4 nodes x 48 = 192
#pragma unroll
    for (int q = 0; q < 2; q++) {
        int idx = t + q * 128;
        if (idx < 192) {
            int nl = idx / 48, g = idx % 48;
            float gi = b_ih[g], gh = b_hh[g];
#pragma unroll
            for (int s = 0; s < 16; s++) {
                gi = fmaf(sH[nl][s], sWih[g * 48 + s], gi);
                gh = fmaf(sH[nl][s], sWhh[g * 16 + s], gh);
            }
#pragma unroll
            for (int m = 0; m < 32; m++) gi = fmaf(sMJ[nl][m], sWih[g * 48 + 16 + m], gi);
            sGI[nl][g] = gi;
            sGH[nl][g] = gh;
        }
    }
    __syncthreads();

    if (t < 64) {
        int nl = t >> 4, s = t & 15;
        float r = sigmoidf(sGI[nl][s] + sGH[nl][s]);
        float z = sigmoidf(sGI[nl][16 + s] + sGH[nl][16 + s]);
        float nv = tanhf(sGI[nl][32 + s] + r * sGH[nl][32 + s]);
        float hn = (1.0f - z) * nv + z * sH[nl][s];
        sHn[nl][s] = hn;
        g_h[(n0 + nl) * 16 + s] = hn;
    }
    __syncthreads();

    if (step < 4) {
        // hi/hj for next step: 4 nodes x 64 c x {hi,hj} = 512 outputs
#pragma unroll
        for (int q = 0; q < 4; q++) {
            int idx = t + q * 128;
            int nl = idx >> 7, rem = idx & 127;
            int c = rem & 63, which = rem >> 6;
            int ng = n0 + nl;
            const float* w = &sW1[c * 35 + (which ? 16 : 0)];
            float s = which ? fmaf(bn[ng], sW1[c * 35 + 34], b1[c]) : bn[ng] * sW1[c * 35 + 33];
#pragma unroll
            for (int sd = 0; sd < 16; sd++) s = fmaf(sHn[nl][sd], w[sd], s);
            if (which) g_hj[ng * 64 + c] = s;
            else       g_hi[ng * 64 + c] = s;
        }
    } else {
        // fused readout for these 4 nodes
#pragma unroll
        for (int q = 0; q < 2; q++) {
            int idx = t + q * 128;
            int nl = idx >> 6, o = idx & 63;
            float s = br1[o];
#pragma unroll
            for (int k = 0; k < 16; k++) s = fmaf(sHn[nl][k], Wr1[o * 16 + k], s);
            sY[nl][o] = fmaxf(s, 0.0f);
        }
        __syncthreads();
#pragma unroll
        for (int q = 0; q < 2; q++) {
            int idx = t + q * 128;
            int nl = idx >> 6, o = idx & 63;
            float s = br2[o];
#pragma unroll
            for (int k = 0; k < 64; k++) s = fmaf(sY[nl][k], Wr2[o * 64 + k], s);
            sR2[nl][o] = fmaxf(s, 0.0f);
        }
        __syncthreads();
        if (t < 8) {
            int nl = t >> 1, o = t & 1;
            float s = br3[o];
#pragma unroll
            for (int k = 0; k < 64; k++) s = fmaf(sR2[nl][k], Wr3[o * 64 + k], s);
            sR3[nl][o] = sigmoidf(s);
        }
        __syncthreads();
        if (t < 8) {
            int nl = t >> 1, o = t & 1;
            out[(n0 + nl) * 2 + o] = sR3[nl][o] / (sR3[nl][0] + sR3[nl][1]);
        }
    }
}

// ============================================================
// host-side PDL launch helper
// ============================================================
static inline void launch_pdl(const void* func, dim3 grid, dim3 block, size_t smem,
                              void** args) {
    cudaLaunchConfig_t cfg = {};
    cfg.gridDim = grid;
    cfg.blockDim = block;
    cfg.dynamicSmemBytes = smem;
    cfg.stream = 0;
    cudaLaunchAttribute attr[1];
    attr[0].id = cudaLaunchAttributeProgrammaticStreamSerialization;
    attr[0].val.programmaticStreamSerializationAllowed = 1;
    cfg.attrs = attr;
    cfg.numAttrs = 1;
    cudaLaunchKernelExC(&cfg, func, args);
}

// ============================================================
extern "C" void kernel_launch(void* const* d_in, const int* in_sizes, int n_in,
                              void* d_out, int out_size) {
    const float* J    = (const float*)d_in[0];
    const float* b    = (const float*)d_in[1];
    const float* W1   = (const float*)d_in[2];
    const float* b1   = (const float*)d_in[3];
    const float* W2   = (const float*)d_in[4];
    const float* b2   = (const float*)d_in[5];
    const float* W3   = (const float*)d_in[6];
    const float* b3   = (const float*)d_in[7];
    const float* W_ih = (const float*)d_in[8];
    const float* b_ih = (const float*)d_in[9];
    const float* W_hh = (const float*)d_in[10];
    const float* b_hh = (const float*)d_in[11];
    const float* Wr1  = (const float*)d_in[12];
    const float* br1  = (const float*)d_in[13];
    const float* Wr2  = (const float*)d_in[14];
    const float* br2  = (const float*)d_in[15];
    const float* Wr3  = (const float*)d_in[16];
    const float* br3  = (const float*)d_in[17];
    float* out = (float*)d_out;

    cudaFuncSetAttribute(edge_tc_kernel, cudaFuncAttributeMaxDynamicSharedMemorySize, SMEM_EDGE);

    init_kernel<<<128, 256>>>(b, W1, b1);
    for (int step = 0; step < 5; step++) {
        {
            void* args[] = {(void*)&J, (void*)&W1, (void*)&W2, (void*)&b2};
            launch_pdl((const void*)edge_tc_kernel, dim3(32, 8), dim3(256), SMEM_EDGE, args);
        }
        {
            void* args[] = {(void*)&W3, (void*)&b3, (void*)&W_ih, (void*)&b_ih,
                            (void*)&W_hh, (void*)&b_hh, (void*)&W1, (void*)&b1,
                            (void*)&b, (void*)&Wr1, (void*)&br1, (void*)&Wr2,
                            (void*)&br2, (void*)&Wr3, (void*)&br3, (void*)&out,
                            (void*)&step};
            launch_pdl((const void*)mj_gru_kernel, dim3(128), dim3(128), 0, args);
        }
    }
}